// round 1
// baseline (speedup 1.0000x reference)
#include <cuda_runtime.h>
#include <math.h>

// Problem constants
#define Bb   32
#define Tt   2048
#define Ee   256
#define Hh   256
#define NLBL 20
#define Mrows (Bb * Tt)   // 65536

// GEMM tiling
#define BM   128
#define BN   64
#define KT   16
#define BMP  132   // padded row for As
#define BNP  68    // padded row for Bs
#define NCHUNK 8   // pooling chunks over T

// Scratch (device globals; no dynamic allocation allowed)
__device__ float g_h[(size_t)Mrows * 512];          // h = concat(h_f, h_r), [B*T, 512]
__device__ float g_psum[Bb * NCHUNK * 512];
__device__ float g_pmax[Bb * NCHUNK * 512];

__device__ __forceinline__ float sigmoidf_(float x) { return 1.0f / (1.0f + expf(-x)); }

// ---------------------------------------------------------------------------
// Kernel A: fused gates-GEMM + LSTM activation.
// For each output column j in [0,512): dir = j>>8 (f or r), jj = j&255.
// Needs W rows jj (i-gate), 512+jj (g-gate), 768+jj (o-gate). f-gate skipped
// since c0 == 0.  h = sigmoid(o)*tanh( sigmoid(i)*tanh(g) ).
// Block: 128 rows x 64 cols, 256 threads, each thread 8x4 micro-tile x 3 gates.
// ---------------------------------------------------------------------------
__global__ __launch_bounds__(256, 1) void gemm_act_kernel(
    const float* __restrict__ X,
    const float* __restrict__ Wf, const float* __restrict__ Wr,
    const float* __restrict__ bihf, const float* __restrict__ bhhf,
    const float* __restrict__ bihr, const float* __restrict__ bhhr)
{
    __shared__ float As[2][KT][BMP];
    __shared__ float Bs[2][3][KT][BNP];

    const int tid = threadIdx.x;
    const int tr  = tid >> 4;       // 0..15 (row group)
    const int tc  = tid & 15;       // 0..15 (col group)
    const int rb  = blockIdx.y * BM;
    const int jb  = blockIdx.x * BN;
    const int dir = (jb >= 256) ? 1 : 0;
    const float* __restrict__ W = dir ? Wr : Wf;
    const int jj0 = jb & 255;

    // A-load assignment: 128 rows x 4 float4-quads = 512 quads; thread handles 2.
    const int ar0 = tid >> 2;         // row 0..63
    const int ar1 = 64 + ar0;         // row 64..127
    const int aq  = tid & 3;          // k-quad 0..3
    // B-load assignment: 64 cols x 4 quads; thread handles 1 per gate.
    const int bc_ = tid >> 2;         // col 0..63
    const int bq  = tid & 3;

    const float* Xp0 = X + (size_t)(rb + ar0) * Ee + aq * 4;
    const float* Xp1 = X + (size_t)(rb + ar1) * Ee + aq * 4;
    const int jjc = jj0 + bc_;
    const float* Wp0 = W + (size_t)(jjc)       * Ee + bq * 4;  // i-gate row
    const float* Wp1 = W + (size_t)(512 + jjc) * Ee + bq * 4;  // g-gate row
    const float* Wp2 = W + (size_t)(768 + jjc) * Ee + bq * 4;  // o-gate row

    float acc[3][8][4];
#pragma unroll
    for (int g = 0; g < 3; g++)
#pragma unroll
        for (int r = 0; r < 8; r++)
#pragma unroll
            for (int c = 0; c < 4; c++) acc[g][r][c] = 0.0f;

    float4 aR0, aR1, bR0, bR1, bR2;

    // Prefetch chunk 0
    aR0 = *(const float4*)(Xp0);
    aR1 = *(const float4*)(Xp1);
    bR0 = *(const float4*)(Wp0);
    bR1 = *(const float4*)(Wp1);
    bR2 = *(const float4*)(Wp2);
    {
        const int kb = aq * 4;
        As[0][kb + 0][ar0] = aR0.x; As[0][kb + 1][ar0] = aR0.y;
        As[0][kb + 2][ar0] = aR0.z; As[0][kb + 3][ar0] = aR0.w;
        As[0][kb + 0][ar1] = aR1.x; As[0][kb + 1][ar1] = aR1.y;
        As[0][kb + 2][ar1] = aR1.z; As[0][kb + 3][ar1] = aR1.w;
        const int kq = bq * 4;
        Bs[0][0][kq + 0][bc_] = bR0.x; Bs[0][0][kq + 1][bc_] = bR0.y;
        Bs[0][0][kq + 2][bc_] = bR0.z; Bs[0][0][kq + 3][bc_] = bR0.w;
        Bs[0][1][kq + 0][bc_] = bR1.x; Bs[0][1][kq + 1][bc_] = bR1.y;
        Bs[0][1][kq + 2][bc_] = bR1.z; Bs[0][1][kq + 3][bc_] = bR1.w;
        Bs[0][2][kq + 0][bc_] = bR2.x; Bs[0][2][kq + 1][bc_] = bR2.y;
        Bs[0][2][kq + 2][bc_] = bR2.z; Bs[0][2][kq + 3][bc_] = bR2.w;
    }
    __syncthreads();

    const int NCK = Ee / KT;  // 16
    for (int ck = 0; ck < NCK; ck++) {
        const int buf = ck & 1;
        if (ck + 1 < NCK) {
            const int k0 = (ck + 1) * KT;
            aR0 = *(const float4*)(Xp0 + k0);
            aR1 = *(const float4*)(Xp1 + k0);
            bR0 = *(const float4*)(Wp0 + k0);
            bR1 = *(const float4*)(Wp1 + k0);
            bR2 = *(const float4*)(Wp2 + k0);
        }
#pragma unroll
        for (int k = 0; k < KT; k++) {
            float4 a0 = *(const float4*)&As[buf][k][tr * 8];
            float4 a1 = *(const float4*)&As[buf][k][tr * 8 + 4];
            float ar[8] = {a0.x, a0.y, a0.z, a0.w, a1.x, a1.y, a1.z, a1.w};
#pragma unroll
            for (int g = 0; g < 3; g++) {
                float4 bv = *(const float4*)&Bs[buf][g][k][tc * 4];
                float bb[4] = {bv.x, bv.y, bv.z, bv.w};
#pragma unroll
                for (int r = 0; r < 8; r++)
#pragma unroll
                    for (int c = 0; c < 4; c++)
                        acc[g][r][c] = fmaf(ar[r], bb[c], acc[g][r][c]);
            }
        }
        if (ck + 1 < NCK) {
            const int nb = buf ^ 1;
            const int kb = aq * 4;
            As[nb][kb + 0][ar0] = aR0.x; As[nb][kb + 1][ar0] = aR0.y;
            As[nb][kb + 2][ar0] = aR0.z; As[nb][kb + 3][ar0] = aR0.w;
            As[nb][kb + 0][ar1] = aR1.x; As[nb][kb + 1][ar1] = aR1.y;
            As[nb][kb + 2][ar1] = aR1.z; As[nb][kb + 3][ar1] = aR1.w;
            const int kq = bq * 4;
            Bs[nb][0][kq + 0][bc_] = bR0.x; Bs[nb][0][kq + 1][bc_] = bR0.y;
            Bs[nb][0][kq + 2][bc_] = bR0.z; Bs[nb][0][kq + 3][bc_] = bR0.w;
            Bs[nb][1][kq + 0][bc_] = bR1.x; Bs[nb][1][kq + 1][bc_] = bR1.y;
            Bs[nb][1][kq + 2][bc_] = bR1.z; Bs[nb][1][kq + 3][bc_] = bR1.w;
            Bs[nb][2][kq + 0][bc_] = bR2.x; Bs[nb][2][kq + 1][bc_] = bR2.y;
            Bs[nb][2][kq + 2][bc_] = bR2.z; Bs[nb][2][kq + 3][bc_] = bR2.w;
            __syncthreads();
        }
    }

    // Epilogue: add biases (b_ih + b_hh), apply LSTM activation, store h.
    const float* __restrict__ bih = dir ? bihr : bihf;
    const float* __restrict__ bhh = dir ? bhhr : bhhf;
    float bi[4], bg[4], bo[4];
#pragma unroll
    for (int c = 0; c < 4; c++) {
        const int j = jj0 + tc * 4 + c;
        bi[c] = bih[j]       + bhh[j];
        bg[c] = bih[512 + j] + bhh[512 + j];
        bo[c] = bih[768 + j] + bhh[768 + j];
    }
#pragma unroll
    for (int r = 0; r < 8; r++) {
        const int row = rb + tr * 8 + r;
        float hv[4];
#pragma unroll
        for (int c = 0; c < 4; c++) {
            const float iv = acc[0][r][c] + bi[c];
            const float gv = acc[1][r][c] + bg[c];
            const float ov = acc[2][r][c] + bo[c];
            const float cs = sigmoidf_(iv) * tanhf(gv);
            hv[c] = sigmoidf_(ov) * tanhf(cs);
        }
        float4 h4; h4.x = hv[0]; h4.y = hv[1]; h4.z = hv[2]; h4.w = hv[3];
        *(float4*)&g_h[(size_t)row * 512 + jb + tc * 4] = h4;
    }
}

// ---------------------------------------------------------------------------
// Kernel B: masked partial pooling. Grid (NCHUNK, B). Each block reduces a
// 256-timestep chunk for one batch into partial sum/max over 512 columns.
// ---------------------------------------------------------------------------
__global__ void pool_kernel(const int* __restrict__ lengths)
{
    const int chunk = blockIdx.x;
    const int b = blockIdx.y;
    const int tid = threadIdx.x;

    int len = lengths[b];
    if (len < 1) len = 1;
    if (len > Tt) len = Tt;

    const int t0 = chunk * (Tt / NCHUNK);
    int t1 = t0 + (Tt / NCHUNK);
    if (t1 > len) t1 = len;

    float s0 = 0.f, s1 = 0.f, m0 = -1e30f, m1 = -1e30f;
    const float* base = g_h + (size_t)b * Tt * 512;
    for (int t = t0; t < t1; t++) {
        const float v0 = base[(size_t)t * 512 + tid];
        const float v1 = base[(size_t)t * 512 + 256 + tid];
        s0 += v0; s1 += v1;
        m0 = fmaxf(m0, v0); m1 = fmaxf(m1, v1);
    }
    const int o = (b * NCHUNK + chunk) * 512;
    g_psum[o + tid]       = s0;
    g_psum[o + 256 + tid] = s1;
    g_pmax[o + tid]       = m0;
    g_pmax[o + 256 + tid] = m1;
}

// ---------------------------------------------------------------------------
// Kernel C: finish pooling (avg = sum/len, concat, relu) + 2-layer MLP.
// One block per batch.
// ---------------------------------------------------------------------------
__global__ void mlp_kernel(const int* __restrict__ lengths,
                           const float* __restrict__ W1, const float* __restrict__ b1,
                           const float* __restrict__ W2, const float* __restrict__ b2,
                           float* __restrict__ out)
{
    __shared__ float doc[1024];
    __shared__ float d1s[256];
    const int b = blockIdx.x;
    const int tid = threadIdx.x;

    int len = lengths[b];
    if (len < 1) len = 1;
    if (len > Tt) len = Tt;
    const float invlen = 1.0f / (float)len;

    for (int jj = tid; jj < 512; jj += 256) {
        float s = 0.f, m = -1e30f;
#pragma unroll
        for (int c = 0; c < NCHUNK; c++) {
            const int o = (b * NCHUNK + c) * 512 + jj;
            s += g_psum[o];
            m = fmaxf(m, g_pmax[o]);
        }
        doc[jj]       = fmaxf(s * invlen, 0.f);  // relu(avg)
        doc[512 + jj] = fmaxf(m, 0.f);           // relu(max)
    }
    __syncthreads();

    float a1 = b1[tid];
#pragma unroll 8
    for (int k = 0; k < 1024; k++)
        a1 = fmaf(W1[(size_t)tid * 1024 + k], doc[k], a1);
    d1s[tid] = a1;
    __syncthreads();

    if (tid < NLBL) {
        float a2 = b2[tid];
#pragma unroll 8
        for (int k = 0; k < 256; k++)
            a2 = fmaf(W2[tid * 256 + k], d1s[k], a2);
        out[b * NLBL + tid] = a2;
    }
}

// ---------------------------------------------------------------------------
extern "C" void kernel_launch(void* const* d_in, const int* in_sizes, int n_in,
                              void* d_out, int out_size)
{
    const float* X    = (const float*)d_in[0];
    const int*   lens = (const int*)  d_in[1];
    const float* Wf   = (const float*)d_in[2];
    const float* bihf = (const float*)d_in[3];
    const float* bhhf = (const float*)d_in[4];
    const float* Wr   = (const float*)d_in[5];
    const float* bihr = (const float*)d_in[6];
    const float* bhhr = (const float*)d_in[7];
    const float* W1   = (const float*)d_in[8];
    const float* b1   = (const float*)d_in[9];
    const float* W2   = (const float*)d_in[10];
    const float* b2   = (const float*)d_in[11];
    float* out = (float*)d_out;

    dim3 gA(512 / BN, Mrows / BM);  // (8, 512)
    gemm_act_kernel<<<gA, 256>>>(X, Wf, Wr, bihf, bhhf, bihr, bhhr);

    dim3 gB(NCHUNK, Bb);
    pool_kernel<<<gB, 256>>>(lens);

    mlp_kernel<<<Bb, 256>>>(lens, W1, b1, W2, b2, out);
}

// round 4
// speedup vs baseline: 1.7842x; 1.7842x over previous
#include <cuda_runtime.h>
#include <cuda_bf16.h>
#include <math.h>
#include <stdint.h>

// Problem constants
#define Bb   32
#define Tt   2048
#define Ee   256
#define Hh   256
#define NLBL 20
#define Mrows (Bb * Tt)   // 65536
#define NCHUNK 8

// ---------------------------------------------------------------------------
// Device scratch
// ---------------------------------------------------------------------------
__device__ unsigned short g_X2[(size_t)Mrows * 512];   // bf16: cols [0,256) hi, [256,512) lo
__device__ unsigned short g_W2[1536 * 512];            // [dir*768+gate*256+jj][hi 256 | lo 256]
__device__ float g_h[(size_t)Mrows * 512];             // h = concat(h_f, h_r)
__device__ float g_psum[Bb * NCHUNK * 512];
__device__ float g_pmax[Bb * NCHUNK * 512];

// ---------------------------------------------------------------------------
// PTX helpers (compute_103-safe: ldmatrix / mma.sync / cp.async only)
// ---------------------------------------------------------------------------
__device__ __forceinline__ uint32_t smem_u32(const void* p) {
    uint32_t a;
    asm("{ .reg .u64 t; cvta.to.shared.u64 t, %1; cvt.u32.u64 %0, t; }" : "=r"(a) : "l"(p));
    return a;
}

__device__ __forceinline__ void cpa16(uint32_t dst, const void* src) {
    asm volatile("cp.async.cg.shared.global [%0], [%1], 16;" :: "r"(dst), "l"(src));
}
#define CPA_COMMIT() asm volatile("cp.async.commit_group;" ::: "memory")
#define CPA_WAIT1()  asm volatile("cp.async.wait_group 1;" ::: "memory")
#define CPA_WAIT0()  asm volatile("cp.async.wait_group 0;" ::: "memory")

#define LDSM_X4(r0, r1, r2, r3, addr) \
    asm volatile("ldmatrix.sync.aligned.m8n8.x4.shared.b16 {%0,%1,%2,%3}, [%4];" \
                 : "=r"(r0), "=r"(r1), "=r"(r2), "=r"(r3) : "r"(addr))

#define MMA_BF16(d, a, b) \
    asm volatile("mma.sync.aligned.m16n8k16.row.col.f32.bf16.bf16.f32 " \
                 "{%0,%1,%2,%3}, {%4,%5,%6,%7}, {%8,%9}, {%0,%1,%2,%3};" \
                 : "+f"((d)[0]), "+f"((d)[1]), "+f"((d)[2]), "+f"((d)[3]) \
                 : "r"((a)[0]), "r"((a)[1]), "r"((a)[2]), "r"((a)[3]), \
                   "r"((b)[0]), "r"((b)[1]))

__device__ __forceinline__ uint32_t sw128(uint32_t off) {
    return off ^ ((off >> 3) & 0x70);
}

// ---------------------------------------------------------------------------
// Convert X -> bf16 hi/lo
// ---------------------------------------------------------------------------
__global__ void conv_x_kernel(const float* __restrict__ X) {
    size_t i = (size_t)blockIdx.x * 256 + threadIdx.x;   // one float4 per thread
    float4 v = reinterpret_cast<const float4*>(X)[i];
    size_t row = i >> 6;
    int k4 = (int)(i & 63);
    float xs[4] = {v.x, v.y, v.z, v.w};
    unsigned short hi[4], lo[4];
#pragma unroll
    for (int j = 0; j < 4; j++) {
        __nv_bfloat16 h = __float2bfloat16(xs[j]);
        __nv_bfloat16 l = __float2bfloat16(xs[j] - __bfloat162float(h));
        hi[j] = __bfloat16_as_ushort(h);
        lo[j] = __bfloat16_as_ushort(l);
    }
    *(ushort4*)(g_X2 + row * 512 + k4 * 4)       = make_ushort4(hi[0], hi[1], hi[2], hi[3]);
    *(ushort4*)(g_X2 + row * 512 + 256 + k4 * 4) = make_ushort4(lo[0], lo[1], lo[2], lo[3]);
}

// Convert W (gather i,g,o rows) -> bf16 hi/lo
__global__ void conv_w_kernel(const float* __restrict__ Wf, const float* __restrict__ Wr) {
    int i = blockIdx.x * 256 + threadIdx.x;
    int n = i >> 6;
    int k4 = i & 63;
    int dir = n / 768;
    int rem = n - dir * 768;
    int gate = rem >> 8;
    int jj = rem & 255;
    int gr = (gate == 0) ? jj : (gate == 1) ? 512 + jj : 768 + jj;
    const float* W = dir ? Wr : Wf;
    float4 v = reinterpret_cast<const float4*>(W)[(size_t)gr * 64 + k4];
    float xs[4] = {v.x, v.y, v.z, v.w};
    unsigned short hi[4], lo[4];
#pragma unroll
    for (int j = 0; j < 4; j++) {
        __nv_bfloat16 h = __float2bfloat16(xs[j]);
        __nv_bfloat16 l = __float2bfloat16(xs[j] - __bfloat162float(h));
        hi[j] = __bfloat16_as_ushort(h);
        lo[j] = __bfloat16_as_ushort(l);
    }
    *(ushort4*)(g_W2 + (size_t)n * 512 + k4 * 4)       = make_ushort4(hi[0], hi[1], hi[2], hi[3]);
    *(ushort4*)(g_W2 + (size_t)n * 512 + 256 + k4 * 4) = make_ushort4(lo[0], lo[1], lo[2], lo[3]);
}

// ---------------------------------------------------------------------------
// HMMA gates-GEMM + LSTM activation.
// Grid (4, 1024): x -> {dir, jhalf} (128 h-cols), y -> 64-row M tile.
// CTA: 256 threads = 8 warps (warp_m = wid&1 over 2x32 rows, warp_n = wid>>1
// over 4x96 N cols). N = 384 = [i(128) | g(128) | o(128)].
// K schedule (Kc=64): s=2c: Xhi_c*Whi_c (load B); s=2c+1: Xlo_c*Whi_c (reuse B);
// s=8+c: Xhi_c*Wlo_c (load B).
// ---------------------------------------------------------------------------
#define KC    64            // halves per stage (128 B rows)
#define SMA_SZ 8192         // 64 rows * 128 B
#define SMB_SZ 49152        // 384 rows * 128 B
#define SMO_B  16384        // after 2 A buffers
#define SMEM_GEMM (SMO_B + 2 * SMB_SZ)   // 114688

__global__ __launch_bounds__(256, 1) void gemm_mma_kernel(
    const float* __restrict__ bihf, const float* __restrict__ bhhf,
    const float* __restrict__ bihr, const float* __restrict__ bhhr)
{
    extern __shared__ char smem[];
    const uint32_t sb = smem_u32(smem);
    const int tid  = threadIdx.x;
    const int wid  = tid >> 5;
    const int lane = tid & 31;
    const int dir   = blockIdx.x >> 1;
    const int jhalf = blockIdx.x & 1;
    const int rb    = blockIdx.y * 64;

    const int warpM = (wid & 1) * 32;      // 0 or 32
    const int warpN = (wid >> 1) * 96;     // 0, 96, 192, 288

    // global source bases
    const unsigned short* Xbase = g_X2 + (size_t)rb * 512;
    const int dirbase = dir * 768;

    // per-thread load coordinates
    const int a_row = tid >> 3;            // 0..31 (plus +32 for second half)
    const int a_c16 = tid & 7;
    // B: 3072 16B units, 12 per thread; unit u = tid + 256*it: n = u>>3, c16 = u&7

    float acc[2][12][4];
#pragma unroll
    for (int i = 0; i < 2; i++)
#pragma unroll
        for (int j = 0; j < 12; j++)
#pragma unroll
            for (int k = 0; k < 4; k++) acc[i][j][k] = 0.0f;

    // ---- stage descriptors ----
    // acol(s), bcol(s) in halves; bload(s); bbuf(s)
    auto acol = [](int s) { return (s < 8) ? ((s & 1) * 256 + (s >> 1) * 64) : ((s - 8) * 64); };
    auto bcol = [](int s) { return (s < 8) ? ((s >> 1) * 64) : (256 + (s - 8) * 64); };
    auto bload = [](int s) { return (s >= 8) || ((s & 1) == 0); };
    auto bbuff = [](int s) { return (s < 8) ? ((s >> 1) & 1) : (s & 1); };

    // ---- load issuers ----
    auto loadA = [&](int s) {
        const int ab = s & 1;
        const int colb = acol(s);
#pragma unroll
        for (int h = 0; h < 2; h++) {
            int row = a_row + h * 32;
            uint32_t off = sw128((uint32_t)(row * 128 + a_c16 * 16));
            cpa16(sb + ab * SMA_SZ + off,
                  Xbase + (size_t)row * 512 + colb + a_c16 * 8);
        }
    };
    auto loadB = [&](int s) {
        const int bbf = bbuff(s);
        const int colb = bcol(s);
#pragma unroll
        for (int it = 0; it < 12; it++) {
            int u = tid + it * 256;
            int n = u >> 3, c16 = u & 7;
            int w2row = dirbase + (n >> 7) * 256 + jhalf * 128 + (n & 127);
            uint32_t off = sw128((uint32_t)(n * 128 + c16 * 16));
            cpa16(sb + SMO_B + bbf * SMB_SZ + off,
                  g_W2 + (size_t)w2row * 512 + colb + c16 * 8);
        }
    };

    // ---- prologue: stage 0 ----
    loadA(0);
    loadB(0);
    CPA_COMMIT();

    // precompute ldsm address components (per lane)
    const int aL_row = ((lane >> 3) & 1) * 8 + (lane & 7);  // row within m16
    const int aL_k   = (lane >> 4);                         // k half (0/1)
    const int bL_n   = (lane >> 4) * 8 + (lane & 7);        // n within 16 (2 tiles)
    const int bL_k   = (lane >> 3) & 1;                     // k half

    for (int s = 0; s < 12; s++) {
        if (s < 11) {
            loadA(s + 1);
            if (bload(s + 1)) loadB(s + 1);
        }
        CPA_COMMIT();
        if (s < 11) { CPA_WAIT1(); } else { CPA_WAIT0(); }
        __syncthreads();

        const uint32_t sa = sb + (s & 1) * SMA_SZ;
        const uint32_t sB = sb + SMO_B + bbuff(s) * SMB_SZ;

#pragma unroll
        for (int kk = 0; kk < 4; kk++) {
            uint32_t afr[2][4];
#pragma unroll
            for (int sub = 0; sub < 2; sub++) {
                int row = warpM + sub * 16 + aL_row;
                uint32_t off = sw128((uint32_t)(row * 128 + (kk * 2 + aL_k) * 16));
                LDSM_X4(afr[sub][0], afr[sub][1], afr[sub][2], afr[sub][3], sa + off);
            }
            uint32_t bfr[12][2];
#pragma unroll
            for (int p = 0; p < 6; p++) {
                int n = warpN + p * 16 + bL_n;
                uint32_t off = sw128((uint32_t)(n * 128 + (kk * 2 + bL_k) * 16));
                LDSM_X4(bfr[2 * p][0], bfr[2 * p][1], bfr[2 * p + 1][0], bfr[2 * p + 1][1],
                        sB + off);
            }
#pragma unroll
            for (int sub = 0; sub < 2; sub++)
#pragma unroll
                for (int nt = 0; nt < 12; nt++)
                    MMA_BF16(acc[sub][nt], afr[sub], bfr[nt]);
        }
        __syncthreads();
    }

    // ---- epilogue: acc -> SMEM (fp32, stride 386), then activation ----
    float* smf = (float*)smem;
    const int g  = lane >> 2;
    const int tg = lane & 3;
#pragma unroll
    for (int sub = 0; sub < 2; sub++) {
#pragma unroll
        for (int nt = 0; nt < 12; nt++) {
            int row0 = warpM + sub * 16 + g;
            int col0 = warpN + nt * 8 + tg * 2;
            *(float2*)&smf[row0 * 386 + col0]       = make_float2(acc[sub][nt][0], acc[sub][nt][1]);
            *(float2*)&smf[(row0 + 8) * 386 + col0] = make_float2(acc[sub][nt][2], acc[sub][nt][3]);
        }
    }
    __syncthreads();

    {
        const int jj = tid & 127;
        const int rh = tid >> 7;
        const float* __restrict__ bih = dir ? bihr : bihf;
        const float* __restrict__ bhh = dir ? bhhr : bhhf;
        const int j = jhalf * 128 + jj;
        const float Bi = bih[j]       + bhh[j];
        const float Bg = bih[512 + j] + bhh[512 + j];
        const float Bo = bih[768 + j] + bhh[768 + j];
        float* __restrict__ hcol = g_h + dir * 256 + jhalf * 128 + jj;
#pragma unroll 4
        for (int r = 0; r < 32; r++) {
            const int row = rh * 32 + r;
            float iv = smf[row * 386 + jj]       + Bi;
            float gv = smf[row * 386 + 128 + jj] + Bg;
            float ov = smf[row * 386 + 256 + jj] + Bo;
            float ei = __expf(-iv);
            float eg = __expf(-2.0f * gv);
            float r1;
            asm("rcp.approx.f32 %0, %1;" : "=f"(r1) : "f"((1.0f + ei) * (1.0f + eg)));
            float cs = (1.0f - eg) * r1;
            float eo = __expf(-ov);
            float ec = __expf(-2.0f * cs);
            float r2;
            asm("rcp.approx.f32 %0, %1;" : "=f"(r2) : "f"((1.0f + eo) * (1.0f + ec)));
            hcol[(size_t)(rb + row) * 512] = (1.0f - ec) * r2;
        }
    }
}

// ---------------------------------------------------------------------------
// Pooling + MLP
// ---------------------------------------------------------------------------
__global__ void pool_kernel(const int* __restrict__ lengths)
{
    const int chunk = blockIdx.x;
    const int b = blockIdx.y;
    const int tid = threadIdx.x;

    int len = lengths[b];
    if (len < 1) len = 1;
    if (len > Tt) len = Tt;

    const int t0 = chunk * (Tt / NCHUNK);
    int t1 = t0 + (Tt / NCHUNK);
    if (t1 > len) t1 = len;

    float s0 = 0.f, s1 = 0.f, m0 = -1e30f, m1 = -1e30f;
    const float* base = g_h + (size_t)b * Tt * 512;
    for (int t = t0; t < t1; t++) {
        const float v0 = base[(size_t)t * 512 + tid];
        const float v1 = base[(size_t)t * 512 + 256 + tid];
        s0 += v0; s1 += v1;
        m0 = fmaxf(m0, v0); m1 = fmaxf(m1, v1);
    }
    const int o = (b * NCHUNK + chunk) * 512;
    g_psum[o + tid]       = s0;
    g_psum[o + 256 + tid] = s1;
    g_pmax[o + tid]       = m0;
    g_pmax[o + 256 + tid] = m1;
}

__global__ void mlp_kernel(const int* __restrict__ lengths,
                           const float* __restrict__ W1, const float* __restrict__ b1,
                           const float* __restrict__ W2, const float* __restrict__ b2,
                           float* __restrict__ out)
{
    __shared__ float doc[1024];
    __shared__ float d1s[256];
    const int b = blockIdx.x;
    const int tid = threadIdx.x;

    int len = lengths[b];
    if (len < 1) len = 1;
    if (len > Tt) len = Tt;
    const float invlen = 1.0f / (float)len;

    for (int jj = tid; jj < 512; jj += 256) {
        float s = 0.f, m = -1e30f;
#pragma unroll
        for (int c = 0; c < NCHUNK; c++) {
            const int o = (b * NCHUNK + c) * 512 + jj;
            s += g_psum[o];
            m = fmaxf(m, g_pmax[o]);
        }
        doc[jj]       = fmaxf(s * invlen, 0.f);
        doc[512 + jj] = fmaxf(m, 0.f);
    }
    __syncthreads();

    float a1 = b1[tid];
#pragma unroll 8
    for (int k = 0; k < 1024; k++)
        a1 = fmaf(W1[(size_t)tid * 1024 + k], doc[k], a1);
    d1s[tid] = a1;
    __syncthreads();

    if (tid < NLBL) {
        float a2 = b2[tid];
#pragma unroll 8
        for (int k = 0; k < 256; k++)
            a2 = fmaf(W2[tid * 256 + k], d1s[k], a2);
        out[b * NLBL + tid] = a2;
    }
}

// ---------------------------------------------------------------------------
extern "C" void kernel_launch(void* const* d_in, const int* in_sizes, int n_in,
                              void* d_out, int out_size)
{
    const float* X    = (const float*)d_in[0];
    const int*   lens = (const int*)  d_in[1];
    const float* Wf   = (const float*)d_in[2];
    const float* bihf = (const float*)d_in[3];
    const float* bhhf = (const float*)d_in[4];
    const float* Wr   = (const float*)d_in[5];
    const float* bihr = (const float*)d_in[6];
    const float* bhhr = (const float*)d_in[7];
    const float* W1   = (const float*)d_in[8];
    const float* b1   = (const float*)d_in[9];
    const float* W2   = (const float*)d_in[10];
    const float* b2   = (const float*)d_in[11];
    float* out = (float*)d_out;

    cudaFuncSetAttribute(gemm_mma_kernel, cudaFuncAttributeMaxDynamicSharedMemorySize, SMEM_GEMM);

    conv_x_kernel<<<16384, 256>>>(X);
    conv_w_kernel<<<384, 256>>>(Wf, Wr);

    dim3 gG(4, 1024);
    gemm_mma_kernel<<<gG, 256, SMEM_GEMM>>>(bihf, bhhf, bihr, bhhr);

    dim3 gB(NCHUNK, Bb);
    pool_kernel<<<gB, 256>>>(lens);

    mlp_kernel<<<Bb, 256>>>(lens, W1, b1, W2, b2, out);
}

// round 5
// speedup vs baseline: 2.8748x; 1.6113x over previous
#include <cuda_runtime.h>
#include <cuda_bf16.h>
#include <math.h>
#include <stdint.h>

// Problem constants
#define Bb   32
#define Tt   2048
#define Ee   256
#define Hh   256
#define NLBL 20
#define Mrows (Bb * Tt)   // 65536
#define NPART 64          // 32-row pooling partials per batch (2048/32)

// ---------------------------------------------------------------------------
// Device scratch
// ---------------------------------------------------------------------------
__device__ unsigned short g_X2[(size_t)Mrows * 512];   // bf16: cols [0,256) hi, [256,512) lo
__device__ unsigned short g_W2[1536 * 512];            // [dir*768+gate*256+jj][hi 256 | lo 256]
__device__ float g_psum[Bb * NPART * 512];
__device__ float g_pmax[Bb * NPART * 512];

// ---------------------------------------------------------------------------
// PTX helpers (compute_103-safe: ldmatrix / mma.sync / cp.async only)
// ---------------------------------------------------------------------------
__device__ __forceinline__ uint32_t smem_u32(const void* p) {
    uint32_t a;
    asm("{ .reg .u64 t; cvta.to.shared.u64 t, %1; cvt.u32.u64 %0, t; }" : "=r"(a) : "l"(p));
    return a;
}

__device__ __forceinline__ void cpa16(uint32_t dst, const void* src) {
    asm volatile("cp.async.cg.shared.global [%0], [%1], 16;" :: "r"(dst), "l"(src));
}
#define CPA_COMMIT() asm volatile("cp.async.commit_group;" ::: "memory")
#define CPA_WAIT1()  asm volatile("cp.async.wait_group 1;" ::: "memory")
#define CPA_WAIT0()  asm volatile("cp.async.wait_group 0;" ::: "memory")

#define LDSM_X4(r0, r1, r2, r3, addr) \
    asm volatile("ldmatrix.sync.aligned.m8n8.x4.shared.b16 {%0,%1,%2,%3}, [%4];" \
                 : "=r"(r0), "=r"(r1), "=r"(r2), "=r"(r3) : "r"(addr))

#define MMA_BF16(d, a, b) \
    asm volatile("mma.sync.aligned.m16n8k16.row.col.f32.bf16.bf16.f32 " \
                 "{%0,%1,%2,%3}, {%4,%5,%6,%7}, {%8,%9}, {%0,%1,%2,%3};" \
                 : "+f"((d)[0]), "+f"((d)[1]), "+f"((d)[2]), "+f"((d)[3]) \
                 : "r"((a)[0]), "r"((a)[1]), "r"((a)[2]), "r"((a)[3]), \
                   "r"((b)[0]), "r"((b)[1]))

__device__ __forceinline__ uint32_t sw128(uint32_t off) {
    return off ^ ((off >> 3) & 0x70);
}

// ---------------------------------------------------------------------------
// Convert X -> bf16 hi/lo (skip rows beyond the batch's length; those rows
// are never read by any consumer thanks to the pooling mask, and g_X2 stays
// zero-initialized there -> deterministic).
// ---------------------------------------------------------------------------
__global__ void conv_x_kernel(const float* __restrict__ X, const int* __restrict__ lengths) {
    size_t i = (size_t)blockIdx.x * 256 + threadIdx.x;   // one float4 per thread
    size_t row = i >> 6;
    int b = (int)(row >> 11);
    int t = (int)(row & 2047);
    int len = lengths[b];
    if (len < 1) len = 1;
    if (len > Tt) len = Tt;
    if (t >= len) return;

    float4 v = reinterpret_cast<const float4*>(X)[i];
    int k4 = (int)(i & 63);
    float xs[4] = {v.x, v.y, v.z, v.w};
    unsigned short hi[4], lo[4];
#pragma unroll
    for (int j = 0; j < 4; j++) {
        __nv_bfloat16 h = __float2bfloat16(xs[j]);
        __nv_bfloat16 l = __float2bfloat16(xs[j] - __bfloat162float(h));
        hi[j] = __bfloat16_as_ushort(h);
        lo[j] = __bfloat16_as_ushort(l);
    }
    *(ushort4*)(g_X2 + row * 512 + k4 * 4)       = make_ushort4(hi[0], hi[1], hi[2], hi[3]);
    *(ushort4*)(g_X2 + row * 512 + 256 + k4 * 4) = make_ushort4(lo[0], lo[1], lo[2], lo[3]);
}

// Convert W (gather i,g,o rows) -> bf16 hi/lo
__global__ void conv_w_kernel(const float* __restrict__ Wf, const float* __restrict__ Wr) {
    int i = blockIdx.x * 256 + threadIdx.x;
    int n = i >> 6;
    int k4 = i & 63;
    int dir = n / 768;
    int rem = n - dir * 768;
    int gate = rem >> 8;
    int jj = rem & 255;
    int gr = (gate == 0) ? jj : (gate == 1) ? 512 + jj : 768 + jj;
    const float* W = dir ? Wr : Wf;
    float4 v = reinterpret_cast<const float4*>(W)[(size_t)gr * 64 + k4];
    float xs[4] = {v.x, v.y, v.z, v.w};
    unsigned short hi[4], lo[4];
#pragma unroll
    for (int j = 0; j < 4; j++) {
        __nv_bfloat16 h = __float2bfloat16(xs[j]);
        __nv_bfloat16 l = __float2bfloat16(xs[j] - __bfloat162float(h));
        hi[j] = __bfloat16_as_ushort(h);
        lo[j] = __bfloat16_as_ushort(l);
    }
    *(ushort4*)(g_W2 + (size_t)n * 512 + k4 * 4)       = make_ushort4(hi[0], hi[1], hi[2], hi[3]);
    *(ushort4*)(g_W2 + (size_t)n * 512 + 256 + k4 * 4) = make_ushort4(lo[0], lo[1], lo[2], lo[3]);
}

// ---------------------------------------------------------------------------
// HMMA gates-GEMM + LSTM activation + fused masked pooling.
// Grid (4, 1024): x -> {dir, jhalf} (128 h-cols), y -> 64-row M tile.
// CTAs whose entire 64-row tile is past lengths[b] early-exit.
// Epilogue produces 32-row masked sum/max partials directly (no g_h).
// ---------------------------------------------------------------------------
#define SMA_SZ 8192         // 64 rows * 128 B
#define SMB_SZ 49152        // 384 rows * 128 B
#define SMO_B  16384        // after 2 A buffers
#define SMEM_GEMM (SMO_B + 2 * SMB_SZ)   // 114688

__global__ __launch_bounds__(256, 1) void gemm_mma_kernel(
    const int* __restrict__ lengths,
    const float* __restrict__ bihf, const float* __restrict__ bhhf,
    const float* __restrict__ bihr, const float* __restrict__ bhhr)
{
    extern __shared__ char smem[];
    const uint32_t sb = smem_u32(smem);
    const int tid  = threadIdx.x;
    const int wid  = tid >> 5;
    const int lane = tid & 31;
    const int dir   = blockIdx.x >> 1;
    const int jhalf = blockIdx.x & 1;
    const int rb    = blockIdx.y * 64;

    const int b      = rb >> 11;
    const int tstart = rb & 2047;
    int len = lengths[b];
    if (len < 1) len = 1;
    if (len > Tt) len = Tt;

    // partial-output coordinates for this thread
    const int jj = tid & 127;
    const int rh = tid >> 7;
    const int pcol = dir * 256 + jhalf * 128 + jj;
    const int pidx = ((b << 6) + (tstart >> 5) + rh) * 512 + pcol;

    if (tstart >= len) {   // entire tile masked out: no GEMM work
        g_psum[pidx] = 0.0f;
        g_pmax[pidx] = -1e30f;
        return;
    }

    const int warpM = (wid & 1) * 32;      // 0 or 32
    const int warpN = (wid >> 1) * 96;     // 0, 96, 192, 288

    const unsigned short* Xbase = g_X2 + (size_t)rb * 512;
    const int dirbase = dir * 768;

    const int a_row = tid >> 3;            // 0..31 (+32 for second half)
    const int a_c16 = tid & 7;

    float acc[2][12][4];
#pragma unroll
    for (int i = 0; i < 2; i++)
#pragma unroll
        for (int j = 0; j < 12; j++)
#pragma unroll
            for (int k = 0; k < 4; k++) acc[i][j][k] = 0.0f;

    // stage descriptors
    auto acol = [](int s) { return (s < 8) ? ((s & 1) * 256 + (s >> 1) * 64) : ((s - 8) * 64); };
    auto bcol = [](int s) { return (s < 8) ? ((s >> 1) * 64) : (256 + (s - 8) * 64); };
    auto bload = [](int s) { return (s >= 8) || ((s & 1) == 0); };
    auto bbuff = [](int s) { return (s < 8) ? ((s >> 1) & 1) : (s & 1); };

    auto loadA = [&](int s) {
        const int ab = s & 1;
        const int colb = acol(s);
#pragma unroll
        for (int h = 0; h < 2; h++) {
            int row = a_row + h * 32;
            uint32_t off = sw128((uint32_t)(row * 128 + a_c16 * 16));
            cpa16(sb + ab * SMA_SZ + off,
                  Xbase + (size_t)row * 512 + colb + a_c16 * 8);
        }
    };
    auto loadB = [&](int s) {
        const int bbf = bbuff(s);
        const int colb = bcol(s);
#pragma unroll
        for (int it = 0; it < 12; it++) {
            int u = tid + it * 256;
            int n = u >> 3, c16 = u & 7;
            int w2row = dirbase + (n >> 7) * 256 + jhalf * 128 + (n & 127);
            uint32_t off = sw128((uint32_t)(n * 128 + c16 * 16));
            cpa16(sb + SMO_B + bbf * SMB_SZ + off,
                  g_W2 + (size_t)w2row * 512 + colb + c16 * 8);
        }
    };

    loadA(0);
    loadB(0);
    CPA_COMMIT();

    const int aL_row = ((lane >> 3) & 1) * 8 + (lane & 7);
    const int aL_k   = (lane >> 4);
    const int bL_n   = (lane >> 4) * 8 + (lane & 7);
    const int bL_k   = (lane >> 3) & 1;

    for (int s = 0; s < 12; s++) {
        if (s < 11) {
            loadA(s + 1);
            if (bload(s + 1)) loadB(s + 1);
        }
        CPA_COMMIT();
        if (s < 11) { CPA_WAIT1(); } else { CPA_WAIT0(); }
        __syncthreads();

        const uint32_t sa = sb + (s & 1) * SMA_SZ;
        const uint32_t sB = sb + SMO_B + bbuff(s) * SMB_SZ;

#pragma unroll
        for (int kk = 0; kk < 4; kk++) {
            uint32_t afr[2][4];
#pragma unroll
            for (int sub = 0; sub < 2; sub++) {
                int row = warpM + sub * 16 + aL_row;
                uint32_t off = sw128((uint32_t)(row * 128 + (kk * 2 + aL_k) * 16));
                LDSM_X4(afr[sub][0], afr[sub][1], afr[sub][2], afr[sub][3], sa + off);
            }
            uint32_t bfr[12][2];
#pragma unroll
            for (int p = 0; p < 6; p++) {
                int n = warpN + p * 16 + bL_n;
                uint32_t off = sw128((uint32_t)(n * 128 + (kk * 2 + bL_k) * 16));
                LDSM_X4(bfr[2 * p][0], bfr[2 * p][1], bfr[2 * p + 1][0], bfr[2 * p + 1][1],
                        sB + off);
            }
#pragma unroll
            for (int sub = 0; sub < 2; sub++)
#pragma unroll
                for (int nt = 0; nt < 12; nt++)
                    MMA_BF16(acc[sub][nt], afr[sub], bfr[nt]);
        }
        __syncthreads();
    }

    // ---- epilogue: acc -> SMEM (fp32, stride 386) ----
    float* smf = (float*)smem;
    {
        const int g  = lane >> 2;
        const int tg = lane & 3;
#pragma unroll
        for (int sub = 0; sub < 2; sub++) {
#pragma unroll
            for (int nt = 0; nt < 12; nt++) {
                int row0 = warpM + sub * 16 + g;
                int col0 = warpN + nt * 8 + tg * 2;
                *(float2*)&smf[row0 * 386 + col0]       = make_float2(acc[sub][nt][0], acc[sub][nt][1]);
                *(float2*)&smf[(row0 + 8) * 386 + col0] = make_float2(acc[sub][nt][2], acc[sub][nt][3]);
            }
        }
    }
    __syncthreads();

    // ---- activation + masked pooling over this thread's 32-row strip ----
    {
        const float* __restrict__ bih = dir ? bihr : bihf;
        const float* __restrict__ bhh = dir ? bhhr : bhhf;
        const int j = jhalf * 128 + jj;
        const float Bi = bih[j]       + bhh[j];
        const float Bg = bih[512 + j] + bhh[512 + j];
        const float Bo = bih[768 + j] + bhh[768 + j];

        int vr = len - tstart - rh * 32;      // valid rows in this strip
        if (vr < 0) vr = 0;
        if (vr > 32) vr = 32;

        float psum = 0.0f, pmax = -1e30f;
        for (int r = 0; r < vr; r++) {
            const int row = rh * 32 + r;
            float iv = smf[row * 386 + jj]       + Bi;
            float gv = smf[row * 386 + 128 + jj] + Bg;
            float ov = smf[row * 386 + 256 + jj] + Bo;
            float ei = __expf(-iv);
            float eg = __expf(-2.0f * gv);
            float r1;
            asm("rcp.approx.f32 %0, %1;" : "=f"(r1) : "f"((1.0f + ei) * (1.0f + eg)));
            float cs = (1.0f - eg) * r1;
            float eo = __expf(-ov);
            float ec = __expf(-2.0f * cs);
            float r2;
            asm("rcp.approx.f32 %0, %1;" : "=f"(r2) : "f"((1.0f + eo) * (1.0f + ec)));
            float h = (1.0f - ec) * r2;
            psum += h;
            pmax = fmaxf(pmax, h);
        }
        g_psum[pidx] = psum;
        g_pmax[pidx] = pmax;
    }
}

// ---------------------------------------------------------------------------
// Final reduce (64 partials/batch) + MLP
// ---------------------------------------------------------------------------
__global__ void mlp_kernel(const int* __restrict__ lengths,
                           const float* __restrict__ W1, const float* __restrict__ b1,
                           const float* __restrict__ W2, const float* __restrict__ b2,
                           float* __restrict__ out)
{
    __shared__ float doc[1024];
    __shared__ float d1s[256];
    const int b = blockIdx.x;
    const int tid = threadIdx.x;

    int len = lengths[b];
    if (len < 1) len = 1;
    if (len > Tt) len = Tt;
    const float invlen = 1.0f / (float)len;

    for (int jj = tid; jj < 512; jj += 256) {
        float s = 0.f, m = -1e30f;
#pragma unroll 8
        for (int p = 0; p < NPART; p++) {
            const int o = (b * NPART + p) * 512 + jj;
            s += g_psum[o];
            m = fmaxf(m, g_pmax[o]);
        }
        doc[jj]       = fmaxf(s * invlen, 0.f);
        doc[512 + jj] = fmaxf(m, 0.f);
    }
    __syncthreads();

    float a1 = b1[tid];
#pragma unroll 8
    for (int k = 0; k < 1024; k++)
        a1 = fmaf(W1[(size_t)tid * 1024 + k], doc[k], a1);
    d1s[tid] = a1;
    __syncthreads();

    if (tid < NLBL) {
        float a2 = b2[tid];
#pragma unroll 8
        for (int k = 0; k < 256; k++)
            a2 = fmaf(W2[tid * 256 + k], d1s[k], a2);
        out[b * NLBL + tid] = a2;
    }
}

// ---------------------------------------------------------------------------
extern "C" void kernel_launch(void* const* d_in, const int* in_sizes, int n_in,
                              void* d_out, int out_size)
{
    const float* X    = (const float*)d_in[0];
    const int*   lens = (const int*)  d_in[1];
    const float* Wf   = (const float*)d_in[2];
    const float* bihf = (const float*)d_in[3];
    const float* bhhf = (const float*)d_in[4];
    const float* Wr   = (const float*)d_in[5];
    const float* bihr = (const float*)d_in[6];
    const float* bhhr = (const float*)d_in[7];
    const float* W1   = (const float*)d_in[8];
    const float* b1   = (const float*)d_in[9];
    const float* W2   = (const float*)d_in[10];
    const float* b2   = (const float*)d_in[11];
    float* out = (float*)d_out;

    cudaFuncSetAttribute(gemm_mma_kernel, cudaFuncAttributeMaxDynamicSharedMemorySize, SMEM_GEMM);

    conv_x_kernel<<<16384, 256>>>(X, lens);
    conv_w_kernel<<<384, 256>>>(Wf, Wr);

    dim3 gG(4, 1024);
    gemm_mma_kernel<<<gG, 256, SMEM_GEMM>>>(lens, bihf, bhhf, bihr, bhhr);

    mlp_kernel<<<Bb, 256>>>(lens, W1, b1, W2, b2, out);
}

// round 6
// speedup vs baseline: 3.4722x; 1.2078x over previous
#include <cuda_runtime.h>
#include <cuda_bf16.h>
#include <math.h>
#include <stdint.h>

// Problem constants
#define Bb   32
#define Tt   2048
#define Ee   256
#define Hh   256
#define NLBL 20
#define Mrows (Bb * Tt)   // 65536
#define NPART 64          // 32-row pooling partials per batch (2048/32)

// ---------------------------------------------------------------------------
// Device scratch
// ---------------------------------------------------------------------------
__device__ unsigned short g_X2[(size_t)Mrows * 512];   // bf16: cols [0,256) hi, [256,512) lo
__device__ unsigned short g_W2[1536 * 512];            // [dir*768+gate*256+jj][hi 256 | lo 256]
__device__ float g_psum[Bb * NPART * 512];
__device__ float g_pmax[Bb * NPART * 512];

// ---------------------------------------------------------------------------
// PTX helpers (compute_103-safe: ldmatrix / mma.sync / cp.async only)
// ---------------------------------------------------------------------------
__device__ __forceinline__ uint32_t smem_u32(const void* p) {
    uint32_t a;
    asm("{ .reg .u64 t; cvta.to.shared.u64 t, %1; cvt.u32.u64 %0, t; }" : "=r"(a) : "l"(p));
    return a;
}

__device__ __forceinline__ void cpa16(uint32_t dst, const void* src) {
    asm volatile("cp.async.cg.shared.global [%0], [%1], 16;" :: "r"(dst), "l"(src));
}
#define CPA_COMMIT() asm volatile("cp.async.commit_group;" ::: "memory")
#define CPA_WAIT1()  asm volatile("cp.async.wait_group 1;" ::: "memory")
#define CPA_WAIT0()  asm volatile("cp.async.wait_group 0;" ::: "memory")

#define LDSM_X4(r0, r1, r2, r3, addr) \
    asm volatile("ldmatrix.sync.aligned.m8n8.x4.shared.b16 {%0,%1,%2,%3}, [%4];" \
                 : "=r"(r0), "=r"(r1), "=r"(r2), "=r"(r3) : "r"(addr))

#define MMA_BF16(d, a, b) \
    asm volatile("mma.sync.aligned.m16n8k16.row.col.f32.bf16.bf16.f32 " \
                 "{%0,%1,%2,%3}, {%4,%5,%6,%7}, {%8,%9}, {%0,%1,%2,%3};" \
                 : "+f"((d)[0]), "+f"((d)[1]), "+f"((d)[2]), "+f"((d)[3]) \
                 : "r"((a)[0]), "r"((a)[1]), "r"((a)[2]), "r"((a)[3]), \
                   "r"((b)[0]), "r"((b)[1]))

__device__ __forceinline__ uint32_t sw128(uint32_t off) {
    return off ^ ((off >> 3) & 0x70);
}

// ---------------------------------------------------------------------------
// Convert X -> bf16 hi/lo (skip rows beyond the batch's length)
// ---------------------------------------------------------------------------
__global__ void conv_x_kernel(const float* __restrict__ X, const int* __restrict__ lengths) {
    size_t i = (size_t)blockIdx.x * 256 + threadIdx.x;   // one float4 per thread
    size_t row = i >> 6;
    int b = (int)(row >> 11);
    int t = (int)(row & 2047);
    int len = lengths[b];
    if (len < 1) len = 1;
    if (len > Tt) len = Tt;
    if (t >= len) return;

    float4 v = reinterpret_cast<const float4*>(X)[i];
    int k4 = (int)(i & 63);
    float xs[4] = {v.x, v.y, v.z, v.w};
    unsigned short hi[4], lo[4];
#pragma unroll
    for (int j = 0; j < 4; j++) {
        __nv_bfloat16 h = __float2bfloat16(xs[j]);
        __nv_bfloat16 l = __float2bfloat16(xs[j] - __bfloat162float(h));
        hi[j] = __bfloat16_as_ushort(h);
        lo[j] = __bfloat16_as_ushort(l);
    }
    *(ushort4*)(g_X2 + row * 512 + k4 * 4)       = make_ushort4(hi[0], hi[1], hi[2], hi[3]);
    *(ushort4*)(g_X2 + row * 512 + 256 + k4 * 4) = make_ushort4(lo[0], lo[1], lo[2], lo[3]);
}

// Convert W (gather i,g,o rows) -> bf16 hi/lo
__global__ void conv_w_kernel(const float* __restrict__ Wf, const float* __restrict__ Wr) {
    int i = blockIdx.x * 256 + threadIdx.x;
    int n = i >> 6;
    int k4 = i & 63;
    int dir = n / 768;
    int rem = n - dir * 768;
    int gate = rem >> 8;
    int jj = rem & 255;
    int gr = (gate == 0) ? jj : (gate == 1) ? 512 + jj : 768 + jj;
    const float* W = dir ? Wr : Wf;
    float4 v = reinterpret_cast<const float4*>(W)[(size_t)gr * 64 + k4];
    float xs[4] = {v.x, v.y, v.z, v.w};
    unsigned short hi[4], lo[4];
#pragma unroll
    for (int j = 0; j < 4; j++) {
        __nv_bfloat16 h = __float2bfloat16(xs[j]);
        __nv_bfloat16 l = __float2bfloat16(xs[j] - __bfloat162float(h));
        hi[j] = __bfloat16_as_ushort(h);
        lo[j] = __bfloat16_as_ushort(l);
    }
    *(ushort4*)(g_W2 + (size_t)n * 512 + k4 * 4)       = make_ushort4(hi[0], hi[1], hi[2], hi[3]);
    *(ushort4*)(g_W2 + (size_t)n * 512 + 256 + k4 * 4) = make_ushort4(lo[0], lo[1], lo[2], lo[3]);
}

// ---------------------------------------------------------------------------
// HMMA gates-GEMM + LSTM activation + fused masked pooling. (unchanged)
// ---------------------------------------------------------------------------
#define SMA_SZ 8192         // 64 rows * 128 B
#define SMB_SZ 49152        // 384 rows * 128 B
#define SMO_B  16384        // after 2 A buffers
#define SMEM_GEMM (SMO_B + 2 * SMB_SZ)   // 114688

__global__ __launch_bounds__(256, 1) void gemm_mma_kernel(
    const int* __restrict__ lengths,
    const float* __restrict__ bihf, const float* __restrict__ bhhf,
    const float* __restrict__ bihr, const float* __restrict__ bhhr)
{
    extern __shared__ char smem[];
    const uint32_t sb = smem_u32(smem);
    const int tid  = threadIdx.x;
    const int wid  = tid >> 5;
    const int lane = tid & 31;
    const int dir   = blockIdx.x >> 1;
    const int jhalf = blockIdx.x & 1;
    const int rb    = blockIdx.y * 64;

    const int b      = rb >> 11;
    const int tstart = rb & 2047;
    int len = lengths[b];
    if (len < 1) len = 1;
    if (len > Tt) len = Tt;

    const int jj = tid & 127;
    const int rh = tid >> 7;
    const int pcol = dir * 256 + jhalf * 128 + jj;
    const int pidx = ((b << 6) + (tstart >> 5) + rh) * 512 + pcol;

    if (tstart >= len) {   // entire tile masked out
        g_psum[pidx] = 0.0f;
        g_pmax[pidx] = -1e30f;
        return;
    }

    const int warpM = (wid & 1) * 32;
    const int warpN = (wid >> 1) * 96;

    const unsigned short* Xbase = g_X2 + (size_t)rb * 512;
    const int dirbase = dir * 768;

    const int a_row = tid >> 3;
    const int a_c16 = tid & 7;

    float acc[2][12][4];
#pragma unroll
    for (int i = 0; i < 2; i++)
#pragma unroll
        for (int j = 0; j < 12; j++)
#pragma unroll
            for (int k = 0; k < 4; k++) acc[i][j][k] = 0.0f;

    auto acol = [](int s) { return (s < 8) ? ((s & 1) * 256 + (s >> 1) * 64) : ((s - 8) * 64); };
    auto bcol = [](int s) { return (s < 8) ? ((s >> 1) * 64) : (256 + (s - 8) * 64); };
    auto bload = [](int s) { return (s >= 8) || ((s & 1) == 0); };
    auto bbuff = [](int s) { return (s < 8) ? ((s >> 1) & 1) : (s & 1); };

    auto loadA = [&](int s) {
        const int ab = s & 1;
        const int colb = acol(s);
#pragma unroll
        for (int h = 0; h < 2; h++) {
            int row = a_row + h * 32;
            uint32_t off = sw128((uint32_t)(row * 128 + a_c16 * 16));
            cpa16(sb + ab * SMA_SZ + off,
                  Xbase + (size_t)row * 512 + colb + a_c16 * 8);
        }
    };
    auto loadB = [&](int s) {
        const int bbf = bbuff(s);
        const int colb = bcol(s);
#pragma unroll
        for (int it = 0; it < 12; it++) {
            int u = tid + it * 256;
            int n = u >> 3, c16 = u & 7;
            int w2row = dirbase + (n >> 7) * 256 + jhalf * 128 + (n & 127);
            uint32_t off = sw128((uint32_t)(n * 128 + c16 * 16));
            cpa16(sb + SMO_B + bbf * SMB_SZ + off,
                  g_W2 + (size_t)w2row * 512 + colb + c16 * 8);
        }
    };

    loadA(0);
    loadB(0);
    CPA_COMMIT();

    const int aL_row = ((lane >> 3) & 1) * 8 + (lane & 7);
    const int aL_k   = (lane >> 4);
    const int bL_n   = (lane >> 4) * 8 + (lane & 7);
    const int bL_k   = (lane >> 3) & 1;

    for (int s = 0; s < 12; s++) {
        if (s < 11) {
            loadA(s + 1);
            if (bload(s + 1)) loadB(s + 1);
        }
        CPA_COMMIT();
        if (s < 11) { CPA_WAIT1(); } else { CPA_WAIT0(); }
        __syncthreads();

        const uint32_t sa = sb + (s & 1) * SMA_SZ;
        const uint32_t sB = sb + SMO_B + bbuff(s) * SMB_SZ;

#pragma unroll
        for (int kk = 0; kk < 4; kk++) {
            uint32_t afr[2][4];
#pragma unroll
            for (int sub = 0; sub < 2; sub++) {
                int row = warpM + sub * 16 + aL_row;
                uint32_t off = sw128((uint32_t)(row * 128 + (kk * 2 + aL_k) * 16));
                LDSM_X4(afr[sub][0], afr[sub][1], afr[sub][2], afr[sub][3], sa + off);
            }
            uint32_t bfr[12][2];
#pragma unroll
            for (int p = 0; p < 6; p++) {
                int n = warpN + p * 16 + bL_n;
                uint32_t off = sw128((uint32_t)(n * 128 + (kk * 2 + bL_k) * 16));
                LDSM_X4(bfr[2 * p][0], bfr[2 * p][1], bfr[2 * p + 1][0], bfr[2 * p + 1][1],
                        sB + off);
            }
#pragma unroll
            for (int sub = 0; sub < 2; sub++)
#pragma unroll
                for (int nt = 0; nt < 12; nt++)
                    MMA_BF16(acc[sub][nt], afr[sub], bfr[nt]);
        }
        __syncthreads();
    }

    // epilogue: acc -> SMEM (fp32, stride 386)
    float* smf = (float*)smem;
    {
        const int g  = lane >> 2;
        const int tg = lane & 3;
#pragma unroll
        for (int sub = 0; sub < 2; sub++) {
#pragma unroll
            for (int nt = 0; nt < 12; nt++) {
                int row0 = warpM + sub * 16 + g;
                int col0 = warpN + nt * 8 + tg * 2;
                *(float2*)&smf[row0 * 386 + col0]       = make_float2(acc[sub][nt][0], acc[sub][nt][1]);
                *(float2*)&smf[(row0 + 8) * 386 + col0] = make_float2(acc[sub][nt][2], acc[sub][nt][3]);
            }
        }
    }
    __syncthreads();

    // activation + masked pooling over this thread's 32-row strip
    {
        const float* __restrict__ bih = dir ? bihr : bihf;
        const float* __restrict__ bhh = dir ? bhhr : bhhf;
        const int j = jhalf * 128 + jj;
        const float Bi = bih[j]       + bhh[j];
        const float Bg = bih[512 + j] + bhh[512 + j];
        const float Bo = bih[768 + j] + bhh[768 + j];

        int vr = len - tstart - rh * 32;
        if (vr < 0) vr = 0;
        if (vr > 32) vr = 32;

        float psum = 0.0f, pmax = -1e30f;
        for (int r = 0; r < vr; r++) {
            const int row = rh * 32 + r;
            float iv = smf[row * 386 + jj]       + Bi;
            float gv = smf[row * 386 + 128 + jj] + Bg;
            float ov = smf[row * 386 + 256 + jj] + Bo;
            float ei = __expf(-iv);
            float eg = __expf(-2.0f * gv);
            float r1;
            asm("rcp.approx.f32 %0, %1;" : "=f"(r1) : "f"((1.0f + ei) * (1.0f + eg)));
            float cs = (1.0f - eg) * r1;
            float eo = __expf(-ov);
            float ec = __expf(-2.0f * cs);
            float r2;
            asm("rcp.approx.f32 %0, %1;" : "=f"(r2) : "f"((1.0f + eo) * (1.0f + ec)));
            float h = (1.0f - ec) * r2;
            psum += h;
            pmax = fmaxf(pmax, h);
        }
        g_psum[pidx] = psum;
        g_pmax[pidx] = pmax;
    }
}

// ---------------------------------------------------------------------------
// Final reduce (64 partials/batch) + MLP — warp-parallel dot products.
// Layer 1: warp w computes outputs w*32..w*32+31; lane l strides k by 32
// (coalesced W1 reads), 5-step shfl reduction per output.
// ---------------------------------------------------------------------------
__global__ void mlp_kernel(const int* __restrict__ lengths,
                           const float* __restrict__ W1, const float* __restrict__ b1,
                           const float* __restrict__ W2, const float* __restrict__ b2,
                           float* __restrict__ out)
{
    __shared__ float doc[1024];
    __shared__ float d1s[256];
    const int b = blockIdx.x;
    const int tid = threadIdx.x;
    const int wid = tid >> 5;
    const int lane = tid & 31;

    int len = lengths[b];
    if (len < 1) len = 1;
    if (len > Tt) len = Tt;
    const float invlen = 1.0f / (float)len;

    for (int jj = tid; jj < 512; jj += 256) {
        float s = 0.f, m = -1e30f;
#pragma unroll 8
        for (int p = 0; p < NPART; p++) {
            const int o = (b * NPART + p) * 512 + jj;
            s += g_psum[o];
            m = fmaxf(m, g_pmax[o]);
        }
        doc[jj]       = fmaxf(s * invlen, 0.f);
        doc[512 + jj] = fmaxf(m, 0.f);
    }
    __syncthreads();

    // Layer 1: d1[n] = b1[n] + dot(W1[n,:], doc)
#pragma unroll 4
    for (int o = 0; o < 32; o++) {
        const int n = wid * 32 + o;
        const float* __restrict__ w1r = W1 + (size_t)n * 1024;
        float s = 0.0f;
#pragma unroll
        for (int k = lane; k < 1024; k += 32)
            s = fmaf(w1r[k], doc[k], s);
#pragma unroll
        for (int off = 16; off > 0; off >>= 1)
            s += __shfl_xor_sync(0xFFFFFFFFu, s, off);
        if (lane == 0) d1s[n] = s + b1[n];
    }
    __syncthreads();

    // Layer 2: out[m] = b2[m] + dot(W2[m,:], d1s) — warp per output, round-robin
    for (int m = wid; m < NLBL; m += 8) {
        const float* __restrict__ w2r = W2 + m * 256;
        float s = 0.0f;
#pragma unroll
        for (int k = lane; k < 256; k += 32)
            s = fmaf(w2r[k], d1s[k], s);
#pragma unroll
        for (int off = 16; off > 0; off >>= 1)
            s += __shfl_xor_sync(0xFFFFFFFFu, s, off);
        if (lane == 0) out[b * NLBL + m] = s + b2[m];
    }
}

// ---------------------------------------------------------------------------
extern "C" void kernel_launch(void* const* d_in, const int* in_sizes, int n_in,
                              void* d_out, int out_size)
{
    const float* X    = (const float*)d_in[0];
    const int*   lens = (const int*)  d_in[1];
    const float* Wf   = (const float*)d_in[2];
    const float* bihf = (const float*)d_in[3];
    const float* bhhf = (const float*)d_in[4];
    const float* Wr   = (const float*)d_in[5];
    const float* bihr = (const float*)d_in[6];
    const float* bhhr = (const float*)d_in[7];
    const float* W1   = (const float*)d_in[8];
    const float* b1   = (const float*)d_in[9];
    const float* W2   = (const float*)d_in[10];
    const float* b2   = (const float*)d_in[11];
    float* out = (float*)d_out;

    cudaFuncSetAttribute(gemm_mma_kernel, cudaFuncAttributeMaxDynamicSharedMemorySize, SMEM_GEMM);

    conv_x_kernel<<<16384, 256>>>(X, lens);
    conv_w_kernel<<<384, 256>>>(Wf, Wr);

    dim3 gG(4, 1024);
    gemm_mma_kernel<<<gG, 256, SMEM_GEMM>>>(lens, bihf, bhhf, bihr, bhhr);

    mlp_kernel<<<Bb, 256>>>(lens, W1, b1, W2, b2, out);
}

// round 7
// speedup vs baseline: 4.1688x; 1.2006x over previous
#include <cuda_runtime.h>
#include <cuda_bf16.h>
#include <math.h>
#include <stdint.h>

// Problem constants
#define Bb   32
#define Tt   2048
#define Ee   256
#define Hh   256
#define NLBL 20
#define Mrows (Bb * Tt)   // 65536
#define NPART 64          // 32-row pooling partials per batch (2048/32)

// ---------------------------------------------------------------------------
// Device scratch
// ---------------------------------------------------------------------------
__device__ unsigned short g_X2[(size_t)Mrows * 512];   // bf16: cols [0,256) hi, [256,512) lo
__device__ unsigned short g_W2[1536 * 512];            // [dir*768+gate*256+jj][hi 256 | lo 256]
__device__ float g_psum[Bb * NPART * 512];
__device__ float g_pmax[Bb * NPART * 512];
__device__ float g_doc[Bb * 1024];                     // [avg-relu 512 | max-relu 512]
__device__ float g_d1[Bb * 256];

// ---------------------------------------------------------------------------
// PTX helpers (compute_103-safe: ldmatrix / mma.sync / cp.async only)
// ---------------------------------------------------------------------------
__device__ __forceinline__ uint32_t smem_u32(const void* p) {
    uint32_t a;
    asm("{ .reg .u64 t; cvta.to.shared.u64 t, %1; cvt.u32.u64 %0, t; }" : "=r"(a) : "l"(p));
    return a;
}

__device__ __forceinline__ void cpa16(uint32_t dst, const void* src) {
    asm volatile("cp.async.cg.shared.global [%0], [%1], 16;" :: "r"(dst), "l"(src));
}
#define CPA_COMMIT() asm volatile("cp.async.commit_group;" ::: "memory")
#define CPA_WAIT1()  asm volatile("cp.async.wait_group 1;" ::: "memory")
#define CPA_WAIT0()  asm volatile("cp.async.wait_group 0;" ::: "memory")

#define LDSM_X4(r0, r1, r2, r3, addr) \
    asm volatile("ldmatrix.sync.aligned.m8n8.x4.shared.b16 {%0,%1,%2,%3}, [%4];" \
                 : "=r"(r0), "=r"(r1), "=r"(r2), "=r"(r3) : "r"(addr))

#define MMA_BF16(d, a, b) \
    asm volatile("mma.sync.aligned.m16n8k16.row.col.f32.bf16.bf16.f32 " \
                 "{%0,%1,%2,%3}, {%4,%5,%6,%7}, {%8,%9}, {%0,%1,%2,%3};" \
                 : "+f"((d)[0]), "+f"((d)[1]), "+f"((d)[2]), "+f"((d)[3]) \
                 : "r"((a)[0]), "r"((a)[1]), "r"((a)[2]), "r"((a)[3]), \
                   "r"((b)[0]), "r"((b)[1]))

__device__ __forceinline__ uint32_t sw128(uint32_t off) {
    return off ^ ((off >> 3) & 0x70);
}

// ---------------------------------------------------------------------------
// Convert X -> bf16 hi/lo (skip rows beyond the batch's length)
// ---------------------------------------------------------------------------
__global__ void conv_x_kernel(const float* __restrict__ X, const int* __restrict__ lengths) {
    size_t i = (size_t)blockIdx.x * 256 + threadIdx.x;   // one float4 per thread
    size_t row = i >> 6;
    int b = (int)(row >> 11);
    int t = (int)(row & 2047);
    int len = lengths[b];
    if (len < 1) len = 1;
    if (len > Tt) len = Tt;
    if (t >= len) return;

    float4 v = reinterpret_cast<const float4*>(X)[i];
    int k4 = (int)(i & 63);
    float xs[4] = {v.x, v.y, v.z, v.w};
    unsigned short hi[4], lo[4];
#pragma unroll
    for (int j = 0; j < 4; j++) {
        __nv_bfloat16 h = __float2bfloat16(xs[j]);
        __nv_bfloat16 l = __float2bfloat16(xs[j] - __bfloat162float(h));
        hi[j] = __bfloat16_as_ushort(h);
        lo[j] = __bfloat16_as_ushort(l);
    }
    *(ushort4*)(g_X2 + row * 512 + k4 * 4)       = make_ushort4(hi[0], hi[1], hi[2], hi[3]);
    *(ushort4*)(g_X2 + row * 512 + 256 + k4 * 4) = make_ushort4(lo[0], lo[1], lo[2], lo[3]);
}

// Convert W (gather i,g,o rows) -> bf16 hi/lo
__global__ void conv_w_kernel(const float* __restrict__ Wf, const float* __restrict__ Wr) {
    int i = blockIdx.x * 256 + threadIdx.x;
    int n = i >> 6;
    int k4 = i & 63;
    int dir = n / 768;
    int rem = n - dir * 768;
    int gate = rem >> 8;
    int jj = rem & 255;
    int gr = (gate == 0) ? jj : (gate == 1) ? 512 + jj : 768 + jj;
    const float* W = dir ? Wr : Wf;
    float4 v = reinterpret_cast<const float4*>(W)[(size_t)gr * 64 + k4];
    float xs[4] = {v.x, v.y, v.z, v.w};
    unsigned short hi[4], lo[4];
#pragma unroll
    for (int j = 0; j < 4; j++) {
        __nv_bfloat16 h = __float2bfloat16(xs[j]);
        __nv_bfloat16 l = __float2bfloat16(xs[j] - __bfloat162float(h));
        hi[j] = __bfloat16_as_ushort(h);
        lo[j] = __bfloat16_as_ushort(l);
    }
    *(ushort4*)(g_W2 + (size_t)n * 512 + k4 * 4)       = make_ushort4(hi[0], hi[1], hi[2], hi[3]);
    *(ushort4*)(g_W2 + (size_t)n * 512 + 256 + k4 * 4) = make_ushort4(lo[0], lo[1], lo[2], lo[3]);
}

// ---------------------------------------------------------------------------
// HMMA gates-GEMM + LSTM activation + fused masked pooling. (unchanged)
// ---------------------------------------------------------------------------
#define SMA_SZ 8192         // 64 rows * 128 B
#define SMB_SZ 49152        // 384 rows * 128 B
#define SMO_B  16384        // after 2 A buffers
#define SMEM_GEMM (SMO_B + 2 * SMB_SZ)   // 114688

__global__ __launch_bounds__(256, 1) void gemm_mma_kernel(
    const int* __restrict__ lengths,
    const float* __restrict__ bihf, const float* __restrict__ bhhf,
    const float* __restrict__ bihr, const float* __restrict__ bhhr)
{
    extern __shared__ char smem[];
    const uint32_t sb = smem_u32(smem);
    const int tid  = threadIdx.x;
    const int wid  = tid >> 5;
    const int lane = tid & 31;
    const int dir   = blockIdx.x >> 1;
    const int jhalf = blockIdx.x & 1;
    const int rb    = blockIdx.y * 64;

    const int b      = rb >> 11;
    const int tstart = rb & 2047;
    int len = lengths[b];
    if (len < 1) len = 1;
    if (len > Tt) len = Tt;

    const int jj = tid & 127;
    const int rh = tid >> 7;
    const int pcol = dir * 256 + jhalf * 128 + jj;
    const int pidx = ((b << 6) + (tstart >> 5) + rh) * 512 + pcol;

    if (tstart >= len) {   // entire tile masked out
        g_psum[pidx] = 0.0f;
        g_pmax[pidx] = -1e30f;
        return;
    }

    const int warpM = (wid & 1) * 32;
    const int warpN = (wid >> 1) * 96;

    const unsigned short* Xbase = g_X2 + (size_t)rb * 512;
    const int dirbase = dir * 768;

    const int a_row = tid >> 3;
    const int a_c16 = tid & 7;

    float acc[2][12][4];
#pragma unroll
    for (int i = 0; i < 2; i++)
#pragma unroll
        for (int j = 0; j < 12; j++)
#pragma unroll
            for (int k = 0; k < 4; k++) acc[i][j][k] = 0.0f;

    auto acol = [](int s) { return (s < 8) ? ((s & 1) * 256 + (s >> 1) * 64) : ((s - 8) * 64); };
    auto bcol = [](int s) { return (s < 8) ? ((s >> 1) * 64) : (256 + (s - 8) * 64); };
    auto bload = [](int s) { return (s >= 8) || ((s & 1) == 0); };
    auto bbuff = [](int s) { return (s < 8) ? ((s >> 1) & 1) : (s & 1); };

    auto loadA = [&](int s) {
        const int ab = s & 1;
        const int colb = acol(s);
#pragma unroll
        for (int h = 0; h < 2; h++) {
            int row = a_row + h * 32;
            uint32_t off = sw128((uint32_t)(row * 128 + a_c16 * 16));
            cpa16(sb + ab * SMA_SZ + off,
                  Xbase + (size_t)row * 512 + colb + a_c16 * 8);
        }
    };
    auto loadB = [&](int s) {
        const int bbf = bbuff(s);
        const int colb = bcol(s);
#pragma unroll
        for (int it = 0; it < 12; it++) {
            int u = tid + it * 256;
            int n = u >> 3, c16 = u & 7;
            int w2row = dirbase + (n >> 7) * 256 + jhalf * 128 + (n & 127);
            uint32_t off = sw128((uint32_t)(n * 128 + c16 * 16));
            cpa16(sb + SMO_B + bbf * SMB_SZ + off,
                  g_W2 + (size_t)w2row * 512 + colb + c16 * 8);
        }
    };

    loadA(0);
    loadB(0);
    CPA_COMMIT();

    const int aL_row = ((lane >> 3) & 1) * 8 + (lane & 7);
    const int aL_k   = (lane >> 4);
    const int bL_n   = (lane >> 4) * 8 + (lane & 7);
    const int bL_k   = (lane >> 3) & 1;

    for (int s = 0; s < 12; s++) {
        if (s < 11) {
            loadA(s + 1);
            if (bload(s + 1)) loadB(s + 1);
        }
        CPA_COMMIT();
        if (s < 11) { CPA_WAIT1(); } else { CPA_WAIT0(); }
        __syncthreads();

        const uint32_t sa = sb + (s & 1) * SMA_SZ;
        const uint32_t sB = sb + SMO_B + bbuff(s) * SMB_SZ;

#pragma unroll
        for (int kk = 0; kk < 4; kk++) {
            uint32_t afr[2][4];
#pragma unroll
            for (int sub = 0; sub < 2; sub++) {
                int row = warpM + sub * 16 + aL_row;
                uint32_t off = sw128((uint32_t)(row * 128 + (kk * 2 + aL_k) * 16));
                LDSM_X4(afr[sub][0], afr[sub][1], afr[sub][2], afr[sub][3], sa + off);
            }
            uint32_t bfr[12][2];
#pragma unroll
            for (int p = 0; p < 6; p++) {
                int n = warpN + p * 16 + bL_n;
                uint32_t off = sw128((uint32_t)(n * 128 + (kk * 2 + bL_k) * 16));
                LDSM_X4(bfr[2 * p][0], bfr[2 * p][1], bfr[2 * p + 1][0], bfr[2 * p + 1][1],
                        sB + off);
            }
#pragma unroll
            for (int sub = 0; sub < 2; sub++)
#pragma unroll
                for (int nt = 0; nt < 12; nt++)
                    MMA_BF16(acc[sub][nt], afr[sub], bfr[nt]);
        }
        __syncthreads();
    }

    // epilogue: acc -> SMEM (fp32, stride 386)
    float* smf = (float*)smem;
    {
        const int g  = lane >> 2;
        const int tg = lane & 3;
#pragma unroll
        for (int sub = 0; sub < 2; sub++) {
#pragma unroll
            for (int nt = 0; nt < 12; nt++) {
                int row0 = warpM + sub * 16 + g;
                int col0 = warpN + nt * 8 + tg * 2;
                *(float2*)&smf[row0 * 386 + col0]       = make_float2(acc[sub][nt][0], acc[sub][nt][1]);
                *(float2*)&smf[(row0 + 8) * 386 + col0] = make_float2(acc[sub][nt][2], acc[sub][nt][3]);
            }
        }
    }
    __syncthreads();

    // activation + masked pooling over this thread's 32-row strip
    {
        const float* __restrict__ bih = dir ? bihr : bihf;
        const float* __restrict__ bhh = dir ? bhhr : bhhf;
        const int j = jhalf * 128 + jj;
        const float Bi = bih[j]       + bhh[j];
        const float Bg = bih[512 + j] + bhh[512 + j];
        const float Bo = bih[768 + j] + bhh[768 + j];

        int vr = len - tstart - rh * 32;
        if (vr < 0) vr = 0;
        if (vr > 32) vr = 32;

        float psum = 0.0f, pmax = -1e30f;
        for (int r = 0; r < vr; r++) {
            const int row = rh * 32 + r;
            float iv = smf[row * 386 + jj]       + Bi;
            float gv = smf[row * 386 + 128 + jj] + Bg;
            float ov = smf[row * 386 + 256 + jj] + Bo;
            float ei = __expf(-iv);
            float eg = __expf(-2.0f * gv);
            float r1;
            asm("rcp.approx.f32 %0, %1;" : "=f"(r1) : "f"((1.0f + ei) * (1.0f + eg)));
            float cs = (1.0f - eg) * r1;
            float eo = __expf(-ov);
            float ec = __expf(-2.0f * cs);
            float r2;
            asm("rcp.approx.f32 %0, %1;" : "=f"(r2) : "f"((1.0f + eo) * (1.0f + ec)));
            float h = (1.0f - ec) * r2;
            psum += h;
            pmax = fmaxf(pmax, h);
        }
        g_psum[pidx] = psum;
        g_pmax[pidx] = pmax;
    }
}

// ---------------------------------------------------------------------------
// Tail kernel 1: reduce 64 partials -> doc (relu(avg) | relu(max)).
// Grid (8, 32): block (colgroup, b). 256 threads = 64 cols x 4 reducers.
// ---------------------------------------------------------------------------
__global__ void reduce_kernel(const int* __restrict__ lengths)
{
    const int b   = blockIdx.y;
    const int col = blockIdx.x * 64 + (threadIdx.x >> 2);
    const int r   = threadIdx.x & 3;

    int len = lengths[b];
    if (len < 1) len = 1;
    if (len > Tt) len = Tt;

    float s = 0.0f, m = -1e30f;
    const float* ps = g_psum + (size_t)b * NPART * 512 + col;
    const float* pm = g_pmax + (size_t)b * NPART * 512 + col;
#pragma unroll
    for (int p = r; p < NPART; p += 4) {
        s += ps[p * 512];
        m = fmaxf(m, pm[p * 512]);
    }
    // reduce across the 4 lanes handling this column (same warp, adjacent lanes)
#pragma unroll
    for (int off = 2; off > 0; off >>= 1) {
        s += __shfl_down_sync(0xFFFFFFFFu, s, off, 4);
        m = fmaxf(m, __shfl_down_sync(0xFFFFFFFFu, m, off, 4));
    }
    if (r == 0) {
        g_doc[b * 1024 + col]       = fmaxf(s / (float)len, 0.0f);
        g_doc[b * 1024 + 512 + col] = fmaxf(m, 0.0f);
    }
}

// ---------------------------------------------------------------------------
// Tail kernel 2: layer 1. Grid (8, 32): block (og, b) computes d1[b][og*32..+32).
// 8 warps x 4 outputs each; doc staged in SMEM; 4 independent FMA chains/warp.
// ---------------------------------------------------------------------------
__global__ void mlp1_kernel(const float* __restrict__ W1, const float* __restrict__ b1)
{
    __shared__ float doc[1024];
    const int b   = blockIdx.y;
    const int og  = blockIdx.x;
    const int tid = threadIdx.x;
    const int wid = tid >> 5;
    const int lane = tid & 31;

    *(float4*)&doc[tid * 4] = *(const float4*)&g_doc[b * 1024 + tid * 4];
    __syncthreads();

    const int n0 = og * 32 + wid * 4;
    const float* __restrict__ w0 = W1 + (size_t)(n0 + 0) * 1024;
    const float* __restrict__ w1 = W1 + (size_t)(n0 + 1) * 1024;
    const float* __restrict__ w2 = W1 + (size_t)(n0 + 2) * 1024;
    const float* __restrict__ w3 = W1 + (size_t)(n0 + 3) * 1024;

    float s0 = 0.f, s1 = 0.f, s2 = 0.f, s3 = 0.f;
#pragma unroll
    for (int k = lane; k < 1024; k += 32) {
        const float d = doc[k];
        s0 = fmaf(w0[k], d, s0);
        s1 = fmaf(w1[k], d, s1);
        s2 = fmaf(w2[k], d, s2);
        s3 = fmaf(w3[k], d, s3);
    }
#pragma unroll
    for (int off = 16; off > 0; off >>= 1) {
        s0 += __shfl_xor_sync(0xFFFFFFFFu, s0, off);
        s1 += __shfl_xor_sync(0xFFFFFFFFu, s1, off);
        s2 += __shfl_xor_sync(0xFFFFFFFFu, s2, off);
        s3 += __shfl_xor_sync(0xFFFFFFFFu, s3, off);
    }
    if (lane == 0) {
        g_d1[b * 256 + n0 + 0] = s0 + b1[n0 + 0];
        g_d1[b * 256 + n0 + 1] = s1 + b1[n0 + 1];
        g_d1[b * 256 + n0 + 2] = s2 + b1[n0 + 2];
        g_d1[b * 256 + n0 + 3] = s3 + b1[n0 + 3];
    }
}

// ---------------------------------------------------------------------------
// Tail kernel 3: layer 2. Grid 32: block per batch.
// ---------------------------------------------------------------------------
__global__ void mlp2_kernel(const float* __restrict__ W2, const float* __restrict__ b2,
                            float* __restrict__ out)
{
    __shared__ float d1s[256];
    const int b   = blockIdx.x;
    const int tid = threadIdx.x;
    const int wid = tid >> 5;
    const int lane = tid & 31;

    d1s[tid] = g_d1[b * 256 + tid];
    __syncthreads();

    for (int m = wid; m < NLBL; m += 8) {
        const float* __restrict__ w2r = W2 + m * 256;
        float s = 0.0f;
#pragma unroll
        for (int k = lane; k < 256; k += 32)
            s = fmaf(w2r[k], d1s[k], s);
#pragma unroll
        for (int off = 16; off > 0; off >>= 1)
            s += __shfl_xor_sync(0xFFFFFFFFu, s, off);
        if (lane == 0) out[b * NLBL + m] = s + b2[m];
    }
}

// ---------------------------------------------------------------------------
extern "C" void kernel_launch(void* const* d_in, const int* in_sizes, int n_in,
                              void* d_out, int out_size)
{
    const float* X    = (const float*)d_in[0];
    const int*   lens = (const int*)  d_in[1];
    const float* Wf   = (const float*)d_in[2];
    const float* bihf = (const float*)d_in[3];
    const float* bhhf = (const float*)d_in[4];
    const float* Wr   = (const float*)d_in[5];
    const float* bihr = (const float*)d_in[6];
    const float* bhhr = (const float*)d_in[7];
    const float* W1   = (const float*)d_in[8];
    const float* b1   = (const float*)d_in[9];
    const float* W2   = (const float*)d_in[10];
    const float* b2   = (const float*)d_in[11];
    float* out = (float*)d_out;

    cudaFuncSetAttribute(gemm_mma_kernel, cudaFuncAttributeMaxDynamicSharedMemorySize, SMEM_GEMM);

    conv_x_kernel<<<16384, 256>>>(X, lens);
    conv_w_kernel<<<384, 256>>>(Wf, Wr);

    dim3 gG(4, 1024);
    gemm_mma_kernel<<<gG, 256, SMEM_GEMM>>>(lens, bihf, bhhf, bihr, bhhr);

    dim3 gR(8, Bb);
    reduce_kernel<<<gR, 256>>>(lens);
    dim3 gM1(8, Bb);
    mlp1_kernel<<<gM1, 256>>>(W1, b1);
    mlp2_kernel<<<Bb, 256>>>(W2, b2, out);
}

// round 8
// speedup vs baseline: 4.3698x; 1.0482x over previous
#include <cuda_runtime.h>
#include <cuda_bf16.h>
#include <math.h>
#include <stdint.h>

// Problem constants
#define Bb   32
#define Tt   2048
#define Ee   256
#define Hh   256
#define NLBL 20
#define Mrows (Bb * Tt)   // 65536
#define NPART 64          // 32-row pooling partials per batch (2048/32)

// ---------------------------------------------------------------------------
// Device scratch — pre-swizzled slab images for bulk copies.
// g_X2s: per 64-row tile, 8 slabs of [64 rows x 128 B] (SW128 within row):
//   slab 2c   = X hi, k-chunk c (64 halves)
//   slab 2c+1 = X lo, k-chunk c
// g_W2s: per (dir,jhalf), 8 slabs of [384 rows x 128 B]:
//   slab c    = W hi, k-chunk c   (rows: gate*128 + jl)
//   slab 4+c  = W lo, k-chunk c
// ---------------------------------------------------------------------------
__device__ __align__(128) unsigned char g_X2s[(size_t)1024 * 8 * 8192];   // 64 MB
__device__ __align__(128) unsigned char g_W2s[(size_t)4 * 8 * 49152];     // 1.5 MB
__device__ float g_psum[Bb * NPART * 512];
__device__ float g_pmax[Bb * NPART * 512];
__device__ float g_doc[Bb * 1024];
__device__ float g_d1[Bb * 256];

// ---------------------------------------------------------------------------
// PTX helpers
// ---------------------------------------------------------------------------
__device__ __forceinline__ uint32_t smem_u32(const void* p) {
    uint32_t a;
    asm("{ .reg .u64 t; cvta.to.shared.u64 t, %1; cvt.u32.u64 %0, t; }" : "=r"(a) : "l"(p));
    return a;
}

#define MBARRIER_INIT(addr, cnt) \
    asm volatile("mbarrier.init.shared.b64 [%0], %1;" :: "r"((uint32_t)(addr)), "r"((uint32_t)(cnt)) : "memory")
#define MBARRIER_INVAL(addr) \
    asm volatile("mbarrier.inval.shared.b64 [%0];" :: "r"((uint32_t)(addr)) : "memory")
#define MBARRIER_EXPECT_TX(addr, bytes) \
    asm volatile("mbarrier.arrive.expect_tx.shared.b64 _, [%0], %1;" :: "r"((uint32_t)(addr)), "r"((uint32_t)(bytes)) : "memory")

#define MBARRIER_WAIT_PARITY(mbar_smem_addr, phase_parity) do { \
    uint32_t _mbar = (uint32_t)(mbar_smem_addr); \
    uint32_t _parity = (uint32_t)(phase_parity); \
    uint32_t _done; \
    asm volatile( \
        "{\n\t.reg .pred p;\n\t" \
        "mbarrier.try_wait.parity.acquire.cta.shared::cta.b64 p, [%1], %2;\n\t" \
        "selp.b32 %0, 1, 0, p;\n\t}" \
        : "=r"(_done) : "r"(_mbar), "r"(_parity) : "memory"); \
    if (!_done) { \
        asm volatile( \
            "{\n\t.reg .pred P1;\n\t" \
            "WAIT_LOOP_%=:\n\t" \
            "mbarrier.try_wait.parity.acquire.cta.shared::cta.b64 P1, [%0], %1, 0x989680;\n\t" \
            "@P1 bra.uni WAIT_DONE_%=;\n\t" \
            "bra.uni WAIT_LOOP_%=;\n\t" \
            "WAIT_DONE_%=:\n\t}" \
            :: "r"(_mbar), "r"(_parity) : "memory"); \
    } \
} while (0)

#define CP_BULK(dst, src, sz, mbar) \
    asm volatile("cp.async.bulk.shared::cluster.global.mbarrier::complete_tx::bytes [%0], [%1], %2, [%3];" \
                 :: "r"((uint32_t)(dst)), "l"(src), "r"((uint32_t)(sz)), "r"((uint32_t)(mbar)) : "memory")

#define LDSM_X4(r0, r1, r2, r3, addr) \
    asm volatile("ldmatrix.sync.aligned.m8n8.x4.shared.b16 {%0,%1,%2,%3}, [%4];" \
                 : "=r"(r0), "=r"(r1), "=r"(r2), "=r"(r3) : "r"(addr))

#define MMA_BF16(d, a, b) \
    asm volatile("mma.sync.aligned.m16n8k16.row.col.f32.bf16.bf16.f32 " \
                 "{%0,%1,%2,%3}, {%4,%5,%6,%7}, {%8,%9}, {%0,%1,%2,%3};" \
                 : "+f"((d)[0]), "+f"((d)[1]), "+f"((d)[2]), "+f"((d)[3]) \
                 : "r"((a)[0]), "r"((a)[1]), "r"((a)[2]), "r"((a)[3]), \
                   "r"((b)[0]), "r"((b)[1]))

__device__ __forceinline__ uint32_t sw128(uint32_t off) {
    return off ^ ((off >> 3) & 0x70);
}

// ---------------------------------------------------------------------------
// Convert X -> pre-swizzled bf16 hi/lo slab images (skip masked rows).
// Thread handles 4 consecutive k of one row: writes one ushort4 into the hi
// slab image and one into the lo slab image.
// ---------------------------------------------------------------------------
__global__ void conv_x_kernel(const float* __restrict__ X, const int* __restrict__ lengths) {
    size_t i = (size_t)blockIdx.x * 256 + threadIdx.x;   // one float4 per thread
    size_t row = i >> 6;
    int b = (int)(row >> 11);
    int t = (int)(row & 2047);
    int len = lengths[b];
    if (len < 1) len = 1;
    if (len > Tt) len = Tt;
    if (t >= len) return;

    int k4 = (int)(i & 63);
    float4 v = reinterpret_cast<const float4*>(X)[i];
    float xs[4] = {v.x, v.y, v.z, v.w};
    unsigned short hi[4], lo[4];
#pragma unroll
    for (int j = 0; j < 4; j++) {
        __nv_bfloat16 h = __float2bfloat16(xs[j]);
        __nv_bfloat16 l = __float2bfloat16(xs[j] - __bfloat162float(h));
        hi[j] = __bfloat16_as_ushort(h);
        lo[j] = __bfloat16_as_ushort(l);
    }

    const int tile = (int)(row >> 6);
    const int r    = (int)(row & 63);
    const int c    = k4 >> 4;               // k-chunk 0..3
    const int q    = (k4 & 15) >> 1;        // 16B unit within row (0..7)
    const int b8   = (k4 & 1) * 8;          // byte offset within unit
    const int unit = q ^ (r & 7);           // SW128

    size_t hi_base = ((size_t)(tile * 8 + 2 * c) * 64 + r) * 128 + unit * 16 + b8;
    size_t lo_base = ((size_t)(tile * 8 + 2 * c + 1) * 64 + r) * 128 + unit * 16 + b8;
    *(ushort4*)(g_X2s + hi_base) = make_ushort4(hi[0], hi[1], hi[2], hi[3]);
    *(ushort4*)(g_X2s + lo_base) = make_ushort4(lo[0], lo[1], lo[2], lo[3]);
}

// Convert W (gather i,g,o rows) -> pre-swizzled slab images.
__global__ void conv_w_kernel(const float* __restrict__ Wf, const float* __restrict__ Wr) {
    int i = blockIdx.x * 256 + threadIdx.x;   // 98304 threads, one float4 each
    int n = i >> 6;
    int k4 = i & 63;
    int dir = n / 768;
    int rem = n - dir * 768;
    int gate = rem >> 8;
    int jj = rem & 255;
    int gr = (gate == 0) ? jj : (gate == 1) ? 512 + jj : 768 + jj;
    const float* W = dir ? Wr : Wf;
    float4 v = reinterpret_cast<const float4*>(W)[(size_t)gr * 64 + k4];
    float xs[4] = {v.x, v.y, v.z, v.w};
    unsigned short hi[4], lo[4];
#pragma unroll
    for (int j = 0; j < 4; j++) {
        __nv_bfloat16 h = __float2bfloat16(xs[j]);
        __nv_bfloat16 l = __float2bfloat16(xs[j] - __bfloat162float(h));
        hi[j] = __bfloat16_as_ushort(h);
        lo[j] = __bfloat16_as_ushort(l);
    }

    const int jhalf = jj >> 7;
    const int jl    = jj & 127;
    const int r3    = gate * 128 + jl;       // B-image row 0..383
    const int c     = k4 >> 4;
    const int q     = (k4 & 15) >> 1;
    const int b8    = (k4 & 1) * 8;
    const int unit  = q ^ (r3 & 7);
    const int img   = (dir * 2 + jhalf) * 8;

    size_t hi_base = ((size_t)(img + c) * 384 + r3) * 128 + unit * 16 + b8;
    size_t lo_base = ((size_t)(img + 4 + c) * 384 + r3) * 128 + unit * 16 + b8;
    *(ushort4*)(g_W2s + hi_base) = make_ushort4(hi[0], hi[1], hi[2], hi[3]);
    *(ushort4*)(g_W2s + lo_base) = make_ushort4(lo[0], lo[1], lo[2], lo[3]);
}

// ---------------------------------------------------------------------------
// HMMA gates-GEMM + LSTM activation + fused masked pooling.
// Loads now via single-thread cp.async.bulk + mbarrier (UBLKCP), the slab
// images are pre-swizzled so SMEM layout is identical to before.
// ---------------------------------------------------------------------------
#define SMA_SZ 8192         // 64 rows * 128 B
#define SMB_SZ 49152        // 384 rows * 128 B
#define SMO_B  16384        // after 2 A buffers
#define SMO_MB (SMO_B + 2 * SMB_SZ)     // 114688: two mbarriers
#define SMEM_GEMM (SMO_MB + 64)          // 114752

__global__ __launch_bounds__(256, 1) void gemm_mma_kernel(
    const int* __restrict__ lengths,
    const float* __restrict__ bihf, const float* __restrict__ bhhf,
    const float* __restrict__ bihr, const float* __restrict__ bhhr)
{
    extern __shared__ char smem[];
    const uint32_t sb = smem_u32(smem);
    const int tid  = threadIdx.x;
    const int wid  = tid >> 5;
    const int lane = tid & 31;
    const int dir   = blockIdx.x >> 1;
    const int jhalf = blockIdx.x & 1;
    const int rb    = blockIdx.y * 64;

    const int b      = rb >> 11;
    const int tstart = rb & 2047;
    int len = lengths[b];
    if (len < 1) len = 1;
    if (len > Tt) len = Tt;

    const int jj = tid & 127;
    const int rh = tid >> 7;
    const int pcol = dir * 256 + jhalf * 128 + jj;
    const int pidx = ((b << 6) + (tstart >> 5) + rh) * 512 + pcol;

    if (tstart >= len) {   // entire tile masked out
        g_psum[pidx] = 0.0f;
        g_pmax[pidx] = -1e30f;
        return;
    }

    const int warpM = (wid & 1) * 32;
    const int warpN = (wid >> 1) * 96;

    const int tile8   = (rb >> 6) * 8;
    const int imgbase = (dir * 2 + jhalf) * 8;

    // stage descriptors
    auto bload = [](int s) { return (s >= 8) || ((s & 1) == 0); };
    auto bbuff = [](int s) { return (s < 8) ? ((s >> 1) & 1) : (s & 1); };
    auto aslab = [](int s) { return (s < 8) ? s : 2 * (s - 8); };
    auto bslab = [](int s) { return (s < 8) ? (s >> 1) : 4 + (s - 8); };

    if (tid == 0) {
        MBARRIER_INIT(sb + SMO_MB, 1);
        MBARRIER_INIT(sb + SMO_MB + 8, 1);
    }
    __syncthreads();

    auto issue = [&](int s) {
        const uint32_t mb = sb + SMO_MB + ((s & 1) << 3);
        const uint32_t bytes = SMA_SZ + (bload(s) ? SMB_SZ : 0);
        MBARRIER_EXPECT_TX(mb, bytes);
        const unsigned char* asrc = g_X2s + (size_t)(tile8 + aslab(s)) * SMA_SZ;
        CP_BULK(sb + (s & 1) * SMA_SZ, asrc, SMA_SZ, mb);
        if (bload(s)) {
            const unsigned char* bsrc = g_W2s + (size_t)(imgbase + bslab(s)) * SMB_SZ;
            CP_BULK(sb + SMO_B + bbuff(s) * SMB_SZ, bsrc, SMB_SZ, mb);
        }
    };

    if (tid == 0) issue(0);

    float acc[2][12][4];
#pragma unroll
    for (int i = 0; i < 2; i++)
#pragma unroll
        for (int j = 0; j < 12; j++)
#pragma unroll
            for (int k = 0; k < 4; k++) acc[i][j][k] = 0.0f;

    const int aL_row = ((lane >> 3) & 1) * 8 + (lane & 7);
    const int aL_k   = (lane >> 4);
    const int bL_n   = (lane >> 4) * 8 + (lane & 7);
    const int bL_k   = (lane >> 3) & 1;

    for (int s = 0; s < 12; s++) {
        if (s < 11 && tid == 0) issue(s + 1);

        MBARRIER_WAIT_PARITY(sb + SMO_MB + ((s & 1) << 3), (s >> 1) & 1);

        const uint32_t sa = sb + (s & 1) * SMA_SZ;
        const uint32_t sB = sb + SMO_B + bbuff(s) * SMB_SZ;

#pragma unroll
        for (int kk = 0; kk < 4; kk++) {
            uint32_t afr[2][4];
#pragma unroll
            for (int sub = 0; sub < 2; sub++) {
                int row = warpM + sub * 16 + aL_row;
                uint32_t off = sw128((uint32_t)(row * 128 + (kk * 2 + aL_k) * 16));
                LDSM_X4(afr[sub][0], afr[sub][1], afr[sub][2], afr[sub][3], sa + off);
            }
            uint32_t bfr[12][2];
#pragma unroll
            for (int p = 0; p < 6; p++) {
                int n = warpN + p * 16 + bL_n;
                uint32_t off = sw128((uint32_t)(n * 128 + (kk * 2 + bL_k) * 16));
                LDSM_X4(bfr[2 * p][0], bfr[2 * p][1], bfr[2 * p + 1][0], bfr[2 * p + 1][1],
                        sB + off);
            }
#pragma unroll
            for (int sub = 0; sub < 2; sub++)
#pragma unroll
                for (int nt = 0; nt < 12; nt++)
                    MMA_BF16(acc[sub][nt], afr[sub], bfr[nt]);
        }
        __syncthreads();
    }

    // epilogue: acc -> SMEM (fp32, stride 386); region < SMO_MB so barriers safe,
    // and all loads are complete by now anyway.
    float* smf = (float*)smem;
    {
        const int g  = lane >> 2;
        const int tg = lane & 3;
#pragma unroll
        for (int sub = 0; sub < 2; sub++) {
#pragma unroll
            for (int nt = 0; nt < 12; nt++) {
                int row0 = warpM + sub * 16 + g;
                int col0 = warpN + nt * 8 + tg * 2;
                *(float2*)&smf[row0 * 386 + col0]       = make_float2(acc[sub][nt][0], acc[sub][nt][1]);
                *(float2*)&smf[(row0 + 8) * 386 + col0] = make_float2(acc[sub][nt][2], acc[sub][nt][3]);
            }
        }
    }
    __syncthreads();

    // activation + masked pooling over this thread's 32-row strip
    {
        const float* __restrict__ bih = dir ? bihr : bihf;
        const float* __restrict__ bhh = dir ? bhhr : bhhf;
        const int j = jhalf * 128 + jj;
        const float Bi = bih[j]       + bhh[j];
        const float Bg = bih[512 + j] + bhh[512 + j];
        const float Bo = bih[768 + j] + bhh[768 + j];

        int vr = len - tstart - rh * 32;
        if (vr < 0) vr = 0;
        if (vr > 32) vr = 32;

        float psum = 0.0f, pmax = -1e30f;
        for (int r = 0; r < vr; r++) {
            const int row = rh * 32 + r;
            float iv = smf[row * 386 + jj]       + Bi;
            float gv = smf[row * 386 + 128 + jj] + Bg;
            float ov = smf[row * 386 + 256 + jj] + Bo;
            float ei = __expf(-iv);
            float eg = __expf(-2.0f * gv);
            float r1;
            asm("rcp.approx.f32 %0, %1;" : "=f"(r1) : "f"((1.0f + ei) * (1.0f + eg)));
            float cs = (1.0f - eg) * r1;
            float eo = __expf(-ov);
            float ec = __expf(-2.0f * cs);
            float r2;
            asm("rcp.approx.f32 %0, %1;" : "=f"(r2) : "f"((1.0f + eo) * (1.0f + ec)));
            float h = (1.0f - ec) * r2;
            psum += h;
            pmax = fmaxf(pmax, h);
        }
        g_psum[pidx] = psum;
        g_pmax[pidx] = pmax;
    }

    __syncthreads();
    if (tid == 0) {
        MBARRIER_INVAL(sb + SMO_MB);
        MBARRIER_INVAL(sb + SMO_MB + 8);
    }
}

// ---------------------------------------------------------------------------
// Tail kernels (unchanged from round 7)
// ---------------------------------------------------------------------------
__global__ void reduce_kernel(const int* __restrict__ lengths)
{
    const int b   = blockIdx.y;
    const int col = blockIdx.x * 64 + (threadIdx.x >> 2);
    const int r   = threadIdx.x & 3;

    int len = lengths[b];
    if (len < 1) len = 1;
    if (len > Tt) len = Tt;

    float s = 0.0f, m = -1e30f;
    const float* ps = g_psum + (size_t)b * NPART * 512 + col;
    const float* pm = g_pmax + (size_t)b * NPART * 512 + col;
#pragma unroll
    for (int p = r; p < NPART; p += 4) {
        s += ps[p * 512];
        m = fmaxf(m, pm[p * 512]);
    }
#pragma unroll
    for (int off = 2; off > 0; off >>= 1) {
        s += __shfl_down_sync(0xFFFFFFFFu, s, off, 4);
        m = fmaxf(m, __shfl_down_sync(0xFFFFFFFFu, m, off, 4));
    }
    if (r == 0) {
        g_doc[b * 1024 + col]       = fmaxf(s / (float)len, 0.0f);
        g_doc[b * 1024 + 512 + col] = fmaxf(m, 0.0f);
    }
}

__global__ void mlp1_kernel(const float* __restrict__ W1, const float* __restrict__ b1)
{
    __shared__ float doc[1024];
    const int b   = blockIdx.y;
    const int og  = blockIdx.x;
    const int tid = threadIdx.x;
    const int wid = tid >> 5;
    const int lane = tid & 31;

    *(float4*)&doc[tid * 4] = *(const float4*)&g_doc[b * 1024 + tid * 4];
    __syncthreads();

    const int n0 = og * 32 + wid * 4;
    const float* __restrict__ w0 = W1 + (size_t)(n0 + 0) * 1024;
    const float* __restrict__ w1 = W1 + (size_t)(n0 + 1) * 1024;
    const float* __restrict__ w2 = W1 + (size_t)(n0 + 2) * 1024;
    const float* __restrict__ w3 = W1 + (size_t)(n0 + 3) * 1024;

    float s0 = 0.f, s1 = 0.f, s2 = 0.f, s3 = 0.f;
#pragma unroll
    for (int k = lane; k < 1024; k += 32) {
        const float d = doc[k];
        s0 = fmaf(w0[k], d, s0);
        s1 = fmaf(w1[k], d, s1);
        s2 = fmaf(w2[k], d, s2);
        s3 = fmaf(w3[k], d, s3);
    }
#pragma unroll
    for (int off = 16; off > 0; off >>= 1) {
        s0 += __shfl_xor_sync(0xFFFFFFFFu, s0, off);
        s1 += __shfl_xor_sync(0xFFFFFFFFu, s1, off);
        s2 += __shfl_xor_sync(0xFFFFFFFFu, s2, off);
        s3 += __shfl_xor_sync(0xFFFFFFFFu, s3, off);
    }
    if (lane == 0) {
        g_d1[b * 256 + n0 + 0] = s0 + b1[n0 + 0];
        g_d1[b * 256 + n0 + 1] = s1 + b1[n0 + 1];
        g_d1[b * 256 + n0 + 2] = s2 + b1[n0 + 2];
        g_d1[b * 256 + n0 + 3] = s3 + b1[n0 + 3];
    }
}

__global__ void mlp2_kernel(const float* __restrict__ W2, const float* __restrict__ b2,
                            float* __restrict__ out)
{
    __shared__ float d1s[256];
    const int b   = blockIdx.x;
    const int tid = threadIdx.x;
    const int wid = tid >> 5;
    const int lane = tid & 31;

    d1s[tid] = g_d1[b * 256 + tid];
    __syncthreads();

    for (int m = wid; m < NLBL; m += 8) {
        const float* __restrict__ w2r = W2 + m * 256;
        float s = 0.0f;
#pragma unroll
        for (int k = lane; k < 256; k += 32)
            s = fmaf(w2r[k], d1s[k], s);
#pragma unroll
        for (int off = 16; off > 0; off >>= 1)
            s += __shfl_xor_sync(0xFFFFFFFFu, s, off);
        if (lane == 0) out[b * NLBL + m] = s + b2[m];
    }
}

// ---------------------------------------------------------------------------
extern "C" void kernel_launch(void* const* d_in, const int* in_sizes, int n_in,
                              void* d_out, int out_size)
{
    const float* X    = (const float*)d_in[0];
    const int*   lens = (const int*)  d_in[1];
    const float* Wf   = (const float*)d_in[2];
    const float* bihf = (const float*)d_in[3];
    const float* bhhf = (const float*)d_in[4];
    const float* Wr   = (const float*)d_in[5];
    const float* bihr = (const float*)d_in[6];
    const float* bhhr = (const float*)d_in[7];
    const float* W1   = (const float*)d_in[8];
    const float* b1   = (const float*)d_in[9];
    const float* W2   = (const float*)d_in[10];
    const float* b2   = (const float*)d_in[11];
    float* out = (float*)d_out;

    cudaFuncSetAttribute(gemm_mma_kernel, cudaFuncAttributeMaxDynamicSharedMemorySize, SMEM_GEMM);

    conv_x_kernel<<<16384, 256>>>(X, lens);
    conv_w_kernel<<<384, 256>>>(Wf, Wr);

    dim3 gG(4, 1024);
    gemm_mma_kernel<<<gG, 256, SMEM_GEMM>>>(lens, bihf, bhhf, bihr, bhhr);

    dim3 gR(8, Bb);
    reduce_kernel<<<gR, 256>>>(lens);
    dim3 gM1(8, Bb);
    mlp1_kernel<<<gM1, 256>>>(W1, b1);
    mlp2_kernel<<<Bb, 256>>>(W2, b2, out);
}

// round 9
// speedup vs baseline: 5.6068x; 1.2831x over previous
#include <cuda_runtime.h>
#include <cuda_bf16.h>
#include <math.h>
#include <stdint.h>

// Problem constants
#define Bb   32
#define Tt   2048
#define Ee   256
#define Hh   256
#define NLBL 20
#define Mrows (Bb * Tt)   // 65536
#define NPART 64          // 32-row pooling partials per batch (2048/32)

// ---------------------------------------------------------------------------
// Device scratch — pre-swizzled slab images for bulk copies.
// g_X2s: per 64-row tile, 8 slabs of [64 rows x 128 B] (SW128 within row):
//   slab 2c = X hi chunk c ; slab 2c+1 = X lo chunk c
// g_W2s: per (dir,jhalf), 8 slabs of [384 rows x 128 B]:
//   slab c = W hi chunk c ; slab 4+c = W lo chunk c
//   row order GATE-INTERLEAVED: n = (jl>>5)*96 + gate*32 + (jl&31)
// ---------------------------------------------------------------------------
__device__ __align__(128) unsigned char g_X2s[(size_t)1024 * 8 * 8192];   // 64 MB
__device__ __align__(128) unsigned char g_W2s[(size_t)4 * 8 * 49152];     // 1.5 MB
__device__ float g_psum[Bb * NPART * 512];
__device__ float g_pmax[Bb * NPART * 512];
__device__ float g_doc[Bb * 1024];
__device__ float g_d1[Bb * 256];

// ---------------------------------------------------------------------------
// PTX helpers
// ---------------------------------------------------------------------------
__device__ __forceinline__ uint32_t smem_u32(const void* p) {
    uint32_t a;
    asm("{ .reg .u64 t; cvta.to.shared.u64 t, %1; cvt.u32.u64 %0, t; }" : "=r"(a) : "l"(p));
    return a;
}

#define MBARRIER_INIT(addr, cnt) \
    asm volatile("mbarrier.init.shared.b64 [%0], %1;" :: "r"((uint32_t)(addr)), "r"((uint32_t)(cnt)) : "memory")
#define MBARRIER_INVAL(addr) \
    asm volatile("mbarrier.inval.shared.b64 [%0];" :: "r"((uint32_t)(addr)) : "memory")
#define MBARRIER_EXPECT_TX(addr, bytes) \
    asm volatile("mbarrier.arrive.expect_tx.shared.b64 _, [%0], %1;" :: "r"((uint32_t)(addr)), "r"((uint32_t)(bytes)) : "memory")

#define MBARRIER_WAIT_PARITY(mbar_smem_addr, phase_parity) do { \
    uint32_t _mbar = (uint32_t)(mbar_smem_addr); \
    uint32_t _parity = (uint32_t)(phase_parity); \
    uint32_t _done; \
    asm volatile( \
        "{\n\t.reg .pred p;\n\t" \
        "mbarrier.try_wait.parity.acquire.cta.shared::cta.b64 p, [%1], %2;\n\t" \
        "selp.b32 %0, 1, 0, p;\n\t}" \
        : "=r"(_done) : "r"(_mbar), "r"(_parity) : "memory"); \
    if (!_done) { \
        asm volatile( \
            "{\n\t.reg .pred P1;\n\t" \
            "WAIT_LOOP_%=:\n\t" \
            "mbarrier.try_wait.parity.acquire.cta.shared::cta.b64 P1, [%0], %1, 0x989680;\n\t" \
            "@P1 bra.uni WAIT_DONE_%=;\n\t" \
            "bra.uni WAIT_LOOP_%=;\n\t" \
            "WAIT_DONE_%=:\n\t}" \
            :: "r"(_mbar), "r"(_parity) : "memory"); \
    } \
} while (0)

#define CP_BULK(dst, src, sz, mbar) \
    asm volatile("cp.async.bulk.shared::cluster.global.mbarrier::complete_tx::bytes [%0], [%1], %2, [%3];" \
                 :: "r"((uint32_t)(dst)), "l"(src), "r"((uint32_t)(sz)), "r"((uint32_t)(mbar)) : "memory")

#define LDSM_X4(r0, r1, r2, r3, addr) \
    asm volatile("ldmatrix.sync.aligned.m8n8.x4.shared.b16 {%0,%1,%2,%3}, [%4];" \
                 : "=r"(r0), "=r"(r1), "=r"(r2), "=r"(r3) : "r"(addr))

#define MMA_BF16(d, a, b0, b1) \
    asm volatile("mma.sync.aligned.m16n8k16.row.col.f32.bf16.bf16.f32 " \
                 "{%0,%1,%2,%3}, {%4,%5,%6,%7}, {%8,%9}, {%0,%1,%2,%3};" \
                 : "+f"((d)[0]), "+f"((d)[1]), "+f"((d)[2]), "+f"((d)[3]) \
                 : "r"((a)[0]), "r"((a)[1]), "r"((a)[2]), "r"((a)[3]), \
                   "r"(b0), "r"(b1))

__device__ __forceinline__ uint32_t sw128(uint32_t off) {
    return off ^ ((off >> 3) & 0x70);
}

// ---------------------------------------------------------------------------
// Convert X -> pre-swizzled bf16 hi/lo slab images (skip masked rows).
// ---------------------------------------------------------------------------
__global__ void conv_x_kernel(const float* __restrict__ X, const int* __restrict__ lengths) {
    size_t i = (size_t)blockIdx.x * 256 + threadIdx.x;   // one float4 per thread
    size_t row = i >> 6;
    int b = (int)(row >> 11);
    int t = (int)(row & 2047);
    int len = lengths[b];
    if (len < 1) len = 1;
    if (len > Tt) len = Tt;
    if (t >= len) return;

    int k4 = (int)(i & 63);
    float4 v = reinterpret_cast<const float4*>(X)[i];
    float xs[4] = {v.x, v.y, v.z, v.w};
    unsigned short hi[4], lo[4];
#pragma unroll
    for (int j = 0; j < 4; j++) {
        __nv_bfloat16 h = __float2bfloat16(xs[j]);
        __nv_bfloat16 l = __float2bfloat16(xs[j] - __bfloat162float(h));
        hi[j] = __bfloat16_as_ushort(h);
        lo[j] = __bfloat16_as_ushort(l);
    }

    const int tile = (int)(row >> 6);
    const int r    = (int)(row & 63);
    const int c    = k4 >> 4;
    const int q    = (k4 & 15) >> 1;
    const int b8   = (k4 & 1) * 8;
    const int unit = q ^ (r & 7);

    size_t hi_base = ((size_t)(tile * 8 + 2 * c) * 64 + r) * 128 + unit * 16 + b8;
    size_t lo_base = ((size_t)(tile * 8 + 2 * c + 1) * 64 + r) * 128 + unit * 16 + b8;
    *(ushort4*)(g_X2s + hi_base) = make_ushort4(hi[0], hi[1], hi[2], hi[3]);
    *(ushort4*)(g_X2s + lo_base) = make_ushort4(lo[0], lo[1], lo[2], lo[3]);
}

// Convert W -> pre-swizzled, GATE-INTERLEAVED slab images.
__global__ void conv_w_kernel(const float* __restrict__ Wf, const float* __restrict__ Wr) {
    int i = blockIdx.x * 256 + threadIdx.x;   // 98304 threads, one float4 each
    int n = i >> 6;
    int k4 = i & 63;
    int dir = n / 768;
    int rem = n - dir * 768;
    int gate = rem >> 8;
    int jj = rem & 255;
    int gr = (gate == 0) ? jj : (gate == 1) ? 512 + jj : 768 + jj;
    const float* W = dir ? Wr : Wf;
    float4 v = reinterpret_cast<const float4*>(W)[(size_t)gr * 64 + k4];
    float xs[4] = {v.x, v.y, v.z, v.w};
    unsigned short hi[4], lo[4];
#pragma unroll
    for (int j = 0; j < 4; j++) {
        __nv_bfloat16 h = __float2bfloat16(xs[j]);
        __nv_bfloat16 l = __float2bfloat16(xs[j] - __bfloat162float(h));
        hi[j] = __bfloat16_as_ushort(h);
        lo[j] = __bfloat16_as_ushort(l);
    }

    const int jhalf = jj >> 7;
    const int jl    = jj & 127;
    // gate-interleaved row: 96-col group (jl>>5) contains i,g,o of same 32 h-cols
    const int r3    = (jl >> 5) * 96 + gate * 32 + (jl & 31);
    const int c     = k4 >> 4;
    const int q     = (k4 & 15) >> 1;
    const int b8    = (k4 & 1) * 8;
    const int unit  = q ^ (r3 & 7);
    const int img   = (dir * 2 + jhalf) * 8;

    size_t hi_base = ((size_t)(img + c) * 384 + r3) * 128 + unit * 16 + b8;
    size_t lo_base = ((size_t)(img + 4 + c) * 384 + r3) * 128 + unit * 16 + b8;
    *(ushort4*)(g_W2s + hi_base) = make_ushort4(hi[0], hi[1], hi[2], hi[3]);
    *(ushort4*)(g_W2s + lo_base) = make_ushort4(lo[0], lo[1], lo[2], lo[3]);
}

// ---------------------------------------------------------------------------
// HMMA gates-GEMM + register-level LSTM activation + fused masked pooling.
// No SMEM epilogue; 2 CTAs/SM.
// Warp wid: warpM = (wid&1)*32 (= 32-row pooling strip), hb = wid>>1 (32 h-cols).
// Warp's 96 N-cols = [i(32)|g(32)|o(32)] of h-cols hb*32..hb*32+31.
// ---------------------------------------------------------------------------
#define SMA_SZ 8192         // 64 rows * 128 B
#define SMB_SZ 49152        // 384 rows * 128 B
#define SMO_B  16384        // after 2 A buffers
#define SMO_MB (SMO_B + 2 * SMB_SZ)     // 114688
#define SMEM_GEMM (SMO_MB + 64)          // 114752 -> 2 CTAs/SM

__global__ __launch_bounds__(256, 2) void gemm_mma_kernel(
    const int* __restrict__ lengths,
    const float* __restrict__ bihf, const float* __restrict__ bhhf,
    const float* __restrict__ bihr, const float* __restrict__ bhhr)
{
    extern __shared__ char smem[];
    const uint32_t sb = smem_u32(smem);
    const int tid  = threadIdx.x;
    const int wid  = tid >> 5;
    const int lane = tid & 31;
    const int dir   = blockIdx.x >> 1;
    const int jhalf = blockIdx.x & 1;
    const int rb    = blockIdx.y * 64;

    const int b      = rb >> 11;
    const int tstart = rb & 2047;
    int len = lengths[b];
    if (len < 1) len = 1;
    if (len > Tt) len = Tt;

    if (tstart >= len) {   // entire tile masked out: write zero partials
        const int jj = tid & 127;
        const int rh = tid >> 7;
        const int pidx = ((b << 6) + (tstart >> 5) + rh) * 512 + dir * 256 + jhalf * 128 + jj;
        g_psum[pidx] = 0.0f;
        g_pmax[pidx] = -1e30f;
        return;
    }

    const int warpM = (wid & 1) * 32;
    const int hb    = wid >> 1;            // 32-h-col group
    const int warpN = hb * 96;

    const int tile8   = (rb >> 6) * 8;
    const int imgbase = (dir * 2 + jhalf) * 8;

    auto bload = [](int s) { return (s >= 8) || ((s & 1) == 0); };
    auto bbuff = [](int s) { return (s < 8) ? ((s >> 1) & 1) : (s & 1); };
    auto aslab = [](int s) { return (s < 8) ? s : 2 * (s - 8); };
    auto bslab = [](int s) { return (s < 8) ? (s >> 1) : 4 + (s - 8); };

    if (tid == 0) {
        MBARRIER_INIT(sb + SMO_MB, 1);
        MBARRIER_INIT(sb + SMO_MB + 8, 1);
    }
    __syncthreads();

    auto issue = [&](int s) {
        const uint32_t mb = sb + SMO_MB + ((s & 1) << 3);
        const uint32_t bytes = SMA_SZ + (bload(s) ? SMB_SZ : 0);
        MBARRIER_EXPECT_TX(mb, bytes);
        const unsigned char* asrc = g_X2s + (size_t)(tile8 + aslab(s)) * SMA_SZ;
        CP_BULK(sb + (s & 1) * SMA_SZ, asrc, SMA_SZ, mb);
        if (bload(s)) {
            const unsigned char* bsrc = g_W2s + (size_t)(imgbase + bslab(s)) * SMB_SZ;
            CP_BULK(sb + SMO_B + bbuff(s) * SMB_SZ, bsrc, SMB_SZ, mb);
        }
    };

    if (tid == 0) issue(0);

    float acc[2][12][4];
#pragma unroll
    for (int i = 0; i < 2; i++)
#pragma unroll
        for (int j = 0; j < 12; j++)
#pragma unroll
            for (int k = 0; k < 4; k++) acc[i][j][k] = 0.0f;

    const int aL_row = ((lane >> 3) & 1) * 8 + (lane & 7);
    const int aL_k   = (lane >> 4);
    const int bL_n   = (lane >> 4) * 8 + (lane & 7);
    const int bL_k   = (lane >> 3) & 1;

    for (int s = 0; s < 12; s++) {
        if (s < 11 && tid == 0) issue(s + 1);

        MBARRIER_WAIT_PARITY(sb + SMO_MB + ((s & 1) << 3), (s >> 1) & 1);

        const uint32_t sa = sb + (s & 1) * SMA_SZ;
        const uint32_t sB = sb + SMO_B + bbuff(s) * SMB_SZ;

#pragma unroll
        for (int kk = 0; kk < 4; kk++) {
            uint32_t afr[2][4];
#pragma unroll
            for (int sub = 0; sub < 2; sub++) {
                int row = warpM + sub * 16 + aL_row;
                uint32_t off = sw128((uint32_t)(row * 128 + (kk * 2 + aL_k) * 16));
                LDSM_X4(afr[sub][0], afr[sub][1], afr[sub][2], afr[sub][3], sa + off);
            }
#pragma unroll
            for (int p = 0; p < 6; p++) {
                uint32_t b0, b1, b2, b3;
                int n = warpN + p * 16 + bL_n;
                uint32_t off = sw128((uint32_t)(n * 128 + (kk * 2 + bL_k) * 16));
                LDSM_X4(b0, b1, b2, b3, sB + off);
                MMA_BF16(acc[0][2 * p],     afr[0], b0, b1);
                MMA_BF16(acc[0][2 * p + 1], afr[0], b2, b3);
                MMA_BF16(acc[1][2 * p],     afr[1], b0, b1);
                MMA_BF16(acc[1][2 * p + 1], afr[1], b2, b3);
            }
        }
        __syncthreads();
    }

    // ---- register-level epilogue: activation + masked pooling, no SMEM ----
    {
        const float* __restrict__ bih = dir ? bihr : bihf;
        const float* __restrict__ bhh = dir ? bhhr : bhhf;
        const int g  = lane >> 2;
        const int tg = lane & 3;

        const int vrw  = len - tstart - warpM;          // valid rows in this strip
        const int prow = (b << 6) + (tstart >> 5) + (wid & 1);
        const int pcb  = dir * 256 + jhalf * 128 + hb * 32;   // col base of this warp

        if (vrw <= 0) {
            if (lane < 4) {
#pragma unroll
                for (int q = 0; q < 4; q++)
#pragma unroll
                    for (int c = 0; c < 2; c++) {
                        const int pc = pcb + q * 8 + 2 * tg + c;
                        g_psum[prow * 512 + pc] = 0.0f;
                        g_pmax[prow * 512 + pc] = -1e30f;
                    }
            }
        } else {
            const bool v0 = (g)      < vrw;
            const bool v1 = (g + 8)  < vrw;
            const bool v2 = (g + 16) < vrw;
            const bool v3 = (g + 24) < vrw;
#pragma unroll
            for (int q = 0; q < 4; q++) {
#pragma unroll
                for (int c = 0; c < 2; c++) {
                    const int jl = hb * 32 + q * 8 + 2 * tg + c;
                    const int j  = jhalf * 128 + jl;
                    const float Bi = bih[j]       + bhh[j];
                    const float Bg = bih[512 + j] + bhh[512 + j];
                    const float Bo = bih[768 + j] + bhh[768 + j];

                    float iv[4] = {acc[0][q][c],     acc[0][q][2 + c],
                                   acc[1][q][c],     acc[1][q][2 + c]};
                    float gv[4] = {acc[0][4 + q][c], acc[0][4 + q][2 + c],
                                   acc[1][4 + q][c], acc[1][4 + q][2 + c]};
                    float ov[4] = {acc[0][8 + q][c], acc[0][8 + q][2 + c],
                                   acc[1][8 + q][c], acc[1][8 + q][2 + c]};
                    const bool vld[4] = {v0, v1, v2, v3};

                    float s = 0.0f, m = -1e30f;
#pragma unroll
                    for (int r = 0; r < 4; r++) {
                        float ei = __expf(-(iv[r] + Bi));
                        float eg = __expf(-2.0f * (gv[r] + Bg));
                        float r1;
                        asm("rcp.approx.f32 %0, %1;" : "=f"(r1) : "f"((1.0f + ei) * (1.0f + eg)));
                        float cs = (1.0f - eg) * r1;
                        float eo = __expf(-(ov[r] + Bo));
                        float ec = __expf(-2.0f * cs);
                        float r2;
                        asm("rcp.approx.f32 %0, %1;" : "=f"(r2) : "f"((1.0f + eo) * (1.0f + ec)));
                        float h = (1.0f - ec) * r2;
                        if (vld[r]) { s += h; m = fmaxf(m, h); }
                    }
                    // reduce across the 8 lanes (g=0..7) sharing this column
#pragma unroll
                    for (int off = 4; off < 32; off <<= 1) {
                        s += __shfl_xor_sync(0xFFFFFFFFu, s, off);
                        m = fmaxf(m, __shfl_xor_sync(0xFFFFFFFFu, m, off));
                    }
                    if (g == 0) {
                        const int pc = pcb + q * 8 + 2 * tg + c;
                        g_psum[prow * 512 + pc] = s;
                        g_pmax[prow * 512 + pc] = m;
                    }
                }
            }
        }
    }

    __syncthreads();
    if (tid == 0) {
        MBARRIER_INVAL(sb + SMO_MB);
        MBARRIER_INVAL(sb + SMO_MB + 8);
    }
}

// ---------------------------------------------------------------------------
// Tail kernels (unchanged)
// ---------------------------------------------------------------------------
__global__ void reduce_kernel(const int* __restrict__ lengths)
{
    const int b   = blockIdx.y;
    const int col = blockIdx.x * 64 + (threadIdx.x >> 2);
    const int r   = threadIdx.x & 3;

    int len = lengths[b];
    if (len < 1) len = 1;
    if (len > Tt) len = Tt;

    float s = 0.0f, m = -1e30f;
    const float* ps = g_psum + (size_t)b * NPART * 512 + col;
    const float* pm = g_pmax + (size_t)b * NPART * 512 + col;
#pragma unroll
    for (int p = r; p < NPART; p += 4) {
        s += ps[p * 512];
        m = fmaxf(m, pm[p * 512]);
    }
#pragma unroll
    for (int off = 2; off > 0; off >>= 1) {
        s += __shfl_down_sync(0xFFFFFFFFu, s, off, 4);
        m = fmaxf(m, __shfl_down_sync(0xFFFFFFFFu, m, off, 4));
    }
    if (r == 0) {
        g_doc[b * 1024 + col]       = fmaxf(s / (float)len, 0.0f);
        g_doc[b * 1024 + 512 + col] = fmaxf(m, 0.0f);
    }
}

__global__ void mlp1_kernel(const float* __restrict__ W1, const float* __restrict__ b1)
{
    __shared__ float doc[1024];
    const int b   = blockIdx.y;
    const int og  = blockIdx.x;
    const int tid = threadIdx.x;
    const int wid = tid >> 5;
    const int lane = tid & 31;

    *(float4*)&doc[tid * 4] = *(const float4*)&g_doc[b * 1024 + tid * 4];
    __syncthreads();

    const int n0 = og * 32 + wid * 4;
    const float* __restrict__ w0 = W1 + (size_t)(n0 + 0) * 1024;
    const float* __restrict__ w1 = W1 + (size_t)(n0 + 1) * 1024;
    const float* __restrict__ w2 = W1 + (size_t)(n0 + 2) * 1024;
    const float* __restrict__ w3 = W1 + (size_t)(n0 + 3) * 1024;

    float s0 = 0.f, s1 = 0.f, s2 = 0.f, s3 = 0.f;
#pragma unroll
    for (int k = lane; k < 1024; k += 32) {
        const float d = doc[k];
        s0 = fmaf(w0[k], d, s0);
        s1 = fmaf(w1[k], d, s1);
        s2 = fmaf(w2[k], d, s2);
        s3 = fmaf(w3[k], d, s3);
    }
#pragma unroll
    for (int off = 16; off > 0; off >>= 1) {
        s0 += __shfl_xor_sync(0xFFFFFFFFu, s0, off);
        s1 += __shfl_xor_sync(0xFFFFFFFFu, s1, off);
        s2 += __shfl_xor_sync(0xFFFFFFFFu, s2, off);
        s3 += __shfl_xor_sync(0xFFFFFFFFu, s3, off);
    }
    if (lane == 0) {
        g_d1[b * 256 + n0 + 0] = s0 + b1[n0 + 0];
        g_d1[b * 256 + n0 + 1] = s1 + b1[n0 + 1];
        g_d1[b * 256 + n0 + 2] = s2 + b1[n0 + 2];
        g_d1[b * 256 + n0 + 3] = s3 + b1[n0 + 3];
    }
}

__global__ void mlp2_kernel(const float* __restrict__ W2, const float* __restrict__ b2,
                            float* __restrict__ out)
{
    __shared__ float d1s[256];
    const int b   = blockIdx.x;
    const int tid = threadIdx.x;
    const int wid = tid >> 5;
    const int lane = tid & 31;

    d1s[tid] = g_d1[b * 256 + tid];
    __syncthreads();

    for (int m = wid; m < NLBL; m += 8) {
        const float* __restrict__ w2r = W2 + m * 256;
        float s = 0.0f;
#pragma unroll
        for (int k = lane; k < 256; k += 32)
            s = fmaf(w2r[k], d1s[k], s);
#pragma unroll
        for (int off = 16; off > 0; off >>= 1)
            s += __shfl_xor_sync(0xFFFFFFFFu, s, off);
        if (lane == 0) out[b * NLBL + m] = s + b2[m];
    }
}

// ---------------------------------------------------------------------------
extern "C" void kernel_launch(void* const* d_in, const int* in_sizes, int n_in,
                              void* d_out, int out_size)
{
    const float* X    = (const float*)d_in[0];
    const int*   lens = (const int*)  d_in[1];
    const float* Wf   = (const float*)d_in[2];
    const float* bihf = (const float*)d_in[3];
    const float* bhhf = (const float*)d_in[4];
    const float* Wr   = (const float*)d_in[5];
    const float* bihr = (const float*)d_in[6];
    const float* bhhr = (const float*)d_in[7];
    const float* W1   = (const float*)d_in[8];
    const float* b1   = (const float*)d_in[9];
    const float* W2   = (const float*)d_in[10];
    const float* b2   = (const float*)d_in[11];
    float* out = (float*)d_out;

    cudaFuncSetAttribute(gemm_mma_kernel, cudaFuncAttributeMaxDynamicSharedMemorySize, SMEM_GEMM);

    conv_x_kernel<<<16384, 256>>>(X, lens);
    conv_w_kernel<<<384, 256>>>(Wf, Wr);

    dim3 gG(4, 1024);
    gemm_mma_kernel<<<gG, 256, SMEM_GEMM>>>(lens, bihf, bhhf, bihr, bhhr);

    dim3 gR(8, Bb);
    reduce_kernel<<<gR, 256>>>(lens);
    dim3 gM1(8, Bb);
    mlp1_kernel<<<gM1, 256>>>(W1, b1);
    mlp2_kernel<<<Bb, 256>>>(W2, b2, out);
}

// round 10
// speedup vs baseline: 6.0893x; 1.0860x over previous
#include <cuda_runtime.h>
#include <cuda_bf16.h>
#include <math.h>
#include <stdint.h>

// Problem constants
#define Bb   32
#define Tt   2048
#define Ee   256
#define Hh   256
#define NLBL 20
#define Mrows (Bb * Tt)   // 65536
#define NPART 64          // 32-row pooling partials per batch (2048/32)

// ---------------------------------------------------------------------------
// Device scratch — pre-swizzled slab images for bulk copies.
// g_X2s: per 64-row tile, 8 slabs of [64 rows x 128 B] (SW128 within row):
//   slab 2c = X hi chunk c ; slab 2c+1 = X lo chunk c
// g_W2s: per (dir,jhalf), 8 slabs of [384 rows x 128 B]:
//   slab c = W hi chunk c ; slab 4+c = W lo chunk c
//   row order GATE-INTERLEAVED: n = (jl>>5)*96 + gate*32 + (jl&31)
// ---------------------------------------------------------------------------
__device__ __align__(128) unsigned char g_X2s[(size_t)1024 * 8 * 8192];   // 64 MB
__device__ __align__(128) unsigned char g_W2s[(size_t)4 * 8 * 49152];     // 1.5 MB
__device__ float g_psum[Bb * NPART * 512];
__device__ float g_pmax[Bb * NPART * 512];
__device__ float g_doc[Bb * 1024];
__device__ float g_d1[Bb * 256];

// ---------------------------------------------------------------------------
// PTX helpers
// ---------------------------------------------------------------------------
__device__ __forceinline__ uint32_t smem_u32(const void* p) {
    uint32_t a;
    asm("{ .reg .u64 t; cvta.to.shared.u64 t, %1; cvt.u32.u64 %0, t; }" : "=r"(a) : "l"(p));
    return a;
}
__device__ __forceinline__ float tanha(float x) {
    float y;
    asm("tanh.approx.f32 %0, %1;" : "=f"(y) : "f"(x));
    return y;
}

#define MBARRIER_INIT(addr, cnt) \
    asm volatile("mbarrier.init.shared.b64 [%0], %1;" :: "r"((uint32_t)(addr)), "r"((uint32_t)(cnt)) : "memory")
#define MBARRIER_INVAL(addr) \
    asm volatile("mbarrier.inval.shared.b64 [%0];" :: "r"((uint32_t)(addr)) : "memory")
#define MBARRIER_EXPECT_TX(addr, bytes) \
    asm volatile("mbarrier.arrive.expect_tx.shared.b64 _, [%0], %1;" :: "r"((uint32_t)(addr)), "r"((uint32_t)(bytes)) : "memory")

#define MBARRIER_WAIT_PARITY(mbar_smem_addr, phase_parity) do { \
    uint32_t _mbar = (uint32_t)(mbar_smem_addr); \
    uint32_t _parity = (uint32_t)(phase_parity); \
    uint32_t _done; \
    asm volatile( \
        "{\n\t.reg .pred p;\n\t" \
        "mbarrier.try_wait.parity.acquire.cta.shared::cta.b64 p, [%1], %2;\n\t" \
        "selp.b32 %0, 1, 0, p;\n\t}" \
        : "=r"(_done) : "r"(_mbar), "r"(_parity) : "memory"); \
    if (!_done) { \
        asm volatile( \
            "{\n\t.reg .pred P1;\n\t" \
            "WAIT_LOOP_%=:\n\t" \
            "mbarrier.try_wait.parity.acquire.cta.shared::cta.b64 P1, [%0], %1, 0x989680;\n\t" \
            "@P1 bra.uni WAIT_DONE_%=;\n\t" \
            "bra.uni WAIT_LOOP_%=;\n\t" \
            "WAIT_DONE_%=:\n\t}" \
            :: "r"(_mbar), "r"(_parity) : "memory"); \
    } \
} while (0)

#define CP_BULK(dst, src, sz, mbar) \
    asm volatile("cp.async.bulk.shared::cluster.global.mbarrier::complete_tx::bytes [%0], [%1], %2, [%3];" \
                 :: "r"((uint32_t)(dst)), "l"(src), "r"((uint32_t)(sz)), "r"((uint32_t)(mbar)) : "memory")

#define LDSM_X4(r0, r1, r2, r3, addr) \
    asm volatile("ldmatrix.sync.aligned.m8n8.x4.shared.b16 {%0,%1,%2,%3}, [%4];" \
                 : "=r"(r0), "=r"(r1), "=r"(r2), "=r"(r3) : "r"(addr))

#define MMA_BF16(d, a, b0, b1) \
    asm volatile("mma.sync.aligned.m16n8k16.row.col.f32.bf16.bf16.f32 " \
                 "{%0,%1,%2,%3}, {%4,%5,%6,%7}, {%8,%9}, {%0,%1,%2,%3};" \
                 : "+f"((d)[0]), "+f"((d)[1]), "+f"((d)[2]), "+f"((d)[3]) \
                 : "r"((a)[0]), "r"((a)[1]), "r"((a)[2]), "r"((a)[3]), \
                   "r"(b0), "r"(b1))

__device__ __forceinline__ uint32_t sw128(uint32_t off) {
    return off ^ ((off >> 3) & 0x70);
}

__device__ __forceinline__ uint32_t pack2(unsigned short a, unsigned short b) {
    return (uint32_t)a | ((uint32_t)b << 16);
}

// ---------------------------------------------------------------------------
// Convert X -> pre-swizzled bf16 hi/lo slab images (skip masked rows).
// Thread handles 8 consecutive k of one row = exactly one 16 B swizzle unit
// per image -> single uint4 store each. Grid 8192 x 256.
// ---------------------------------------------------------------------------
__global__ void conv_x_kernel(const float* __restrict__ X, const int* __restrict__ lengths) {
    size_t i = (size_t)blockIdx.x * 256 + threadIdx.x;   // 2M threads
    size_t row = i >> 5;
    int m = (int)(i & 31);                               // 8-k group 0..31
    int b = (int)(row >> 11);
    int t = (int)(row & 2047);
    int len = lengths[b];
    if (len < 1) len = 1;
    if (len > Tt) len = Tt;
    if (t >= len) return;

    const float4* xp = reinterpret_cast<const float4*>(X + row * 256 + m * 8);
    float4 v0 = xp[0];
    float4 v1 = xp[1];
    float xs[8] = {v0.x, v0.y, v0.z, v0.w, v1.x, v1.y, v1.z, v1.w};
    unsigned short hi[8], lo[8];
#pragma unroll
    for (int j = 0; j < 8; j++) {
        __nv_bfloat16 h = __float2bfloat16(xs[j]);
        __nv_bfloat16 l = __float2bfloat16(xs[j] - __bfloat162float(h));
        hi[j] = __bfloat16_as_ushort(h);
        lo[j] = __bfloat16_as_ushort(l);
    }

    const int tile = (int)(row >> 6);
    const int r    = (int)(row & 63);
    const int c    = m >> 3;                 // k-chunk 0..3
    const int unit = (m & 7) ^ (r & 7);      // SW128

    uint4 hv = make_uint4(pack2(hi[0], hi[1]), pack2(hi[2], hi[3]),
                          pack2(hi[4], hi[5]), pack2(hi[6], hi[7]));
    uint4 lv = make_uint4(pack2(lo[0], lo[1]), pack2(lo[2], lo[3]),
                          pack2(lo[4], lo[5]), pack2(lo[6], lo[7]));
    size_t hi_base = ((size_t)(tile * 8 + 2 * c) * 64 + r) * 128 + unit * 16;
    size_t lo_base = ((size_t)(tile * 8 + 2 * c + 1) * 64 + r) * 128 + unit * 16;
    *(uint4*)(g_X2s + hi_base) = hv;
    *(uint4*)(g_X2s + lo_base) = lv;
}

// Convert W -> pre-swizzled, GATE-INTERLEAVED slab images. Grid 192 x 256.
__global__ void conv_w_kernel(const float* __restrict__ Wf, const float* __restrict__ Wr) {
    int i = blockIdx.x * 256 + threadIdx.x;   // 49152 threads
    int n = i >> 5;                            // 0..1535
    int m = i & 31;
    int dir = n / 768;
    int rem = n - dir * 768;
    int gate = rem >> 8;
    int jj = rem & 255;
    int gr = (gate == 0) ? jj : (gate == 1) ? 512 + jj : 768 + jj;
    const float* W = dir ? Wr : Wf;
    const float4* wp = reinterpret_cast<const float4*>(W + (size_t)gr * 256 + m * 8);
    float4 v0 = wp[0];
    float4 v1 = wp[1];
    float xs[8] = {v0.x, v0.y, v0.z, v0.w, v1.x, v1.y, v1.z, v1.w};
    unsigned short hi[8], lo[8];
#pragma unroll
    for (int j = 0; j < 8; j++) {
        __nv_bfloat16 h = __float2bfloat16(xs[j]);
        __nv_bfloat16 l = __float2bfloat16(xs[j] - __bfloat162float(h));
        hi[j] = __bfloat16_as_ushort(h);
        lo[j] = __bfloat16_as_ushort(l);
    }

    const int jhalf = jj >> 7;
    const int jl    = jj & 127;
    const int r3    = (jl >> 5) * 96 + gate * 32 + (jl & 31);
    const int c     = m >> 3;
    const int unit  = (m & 7) ^ (r3 & 7);
    const int img   = (dir * 2 + jhalf) * 8;

    uint4 hv = make_uint4(pack2(hi[0], hi[1]), pack2(hi[2], hi[3]),
                          pack2(hi[4], hi[5]), pack2(hi[6], hi[7]));
    uint4 lv = make_uint4(pack2(lo[0], lo[1]), pack2(lo[2], lo[3]),
                          pack2(lo[4], lo[5]), pack2(lo[6], lo[7]));
    size_t hi_base = ((size_t)(img + c) * 384 + r3) * 128 + unit * 16;
    size_t lo_base = ((size_t)(img + 4 + c) * 384 + r3) * 128 + unit * 16;
    *(uint4*)(g_W2s + hi_base) = hv;
    *(uint4*)(g_W2s + lo_base) = lv;
}

// ---------------------------------------------------------------------------
// HMMA gates-GEMM + register-level LSTM activation (tanh.approx) + fused
// masked pooling. 2 CTAs/SM.
// ---------------------------------------------------------------------------
#define SMA_SZ 8192         // 64 rows * 128 B
#define SMB_SZ 49152        // 384 rows * 128 B
#define SMO_B  16384        // after 2 A buffers
#define SMO_MB (SMO_B + 2 * SMB_SZ)     // 114688
#define SMEM_GEMM (SMO_MB + 64)          // 114752 -> 2 CTAs/SM

__global__ __launch_bounds__(256, 2) void gemm_mma_kernel(
    const int* __restrict__ lengths,
    const float* __restrict__ bihf, const float* __restrict__ bhhf,
    const float* __restrict__ bihr, const float* __restrict__ bhhr)
{
    extern __shared__ char smem[];
    const uint32_t sb = smem_u32(smem);
    const int tid  = threadIdx.x;
    const int wid  = tid >> 5;
    const int lane = tid & 31;
    const int dir   = blockIdx.x >> 1;
    const int jhalf = blockIdx.x & 1;
    const int rb    = blockIdx.y * 64;

    const int b      = rb >> 11;
    const int tstart = rb & 2047;
    int len = lengths[b];
    if (len < 1) len = 1;
    if (len > Tt) len = Tt;

    if (tstart >= len) {   // entire tile masked out: write zero partials
        const int jj = tid & 127;
        const int rh = tid >> 7;
        const int pidx = ((b << 6) + (tstart >> 5) + rh) * 512 + dir * 256 + jhalf * 128 + jj;
        g_psum[pidx] = 0.0f;
        g_pmax[pidx] = -1e30f;
        return;
    }

    const int warpM = (wid & 1) * 32;
    const int hb    = wid >> 1;            // 32-h-col group
    const int warpN = hb * 96;

    const int tile8   = (rb >> 6) * 8;
    const int imgbase = (dir * 2 + jhalf) * 8;

    auto bload = [](int s) { return (s >= 8) || ((s & 1) == 0); };
    auto bbuff = [](int s) { return (s < 8) ? ((s >> 1) & 1) : (s & 1); };
    auto aslab = [](int s) { return (s < 8) ? s : 2 * (s - 8); };
    auto bslab = [](int s) { return (s < 8) ? (s >> 1) : 4 + (s - 8); };

    if (tid == 0) {
        MBARRIER_INIT(sb + SMO_MB, 1);
        MBARRIER_INIT(sb + SMO_MB + 8, 1);
    }
    __syncthreads();

    auto issue = [&](int s) {
        const uint32_t mb = sb + SMO_MB + ((s & 1) << 3);
        const uint32_t bytes = SMA_SZ + (bload(s) ? SMB_SZ : 0);
        MBARRIER_EXPECT_TX(mb, bytes);
        const unsigned char* asrc = g_X2s + (size_t)(tile8 + aslab(s)) * SMA_SZ;
        CP_BULK(sb + (s & 1) * SMA_SZ, asrc, SMA_SZ, mb);
        if (bload(s)) {
            const unsigned char* bsrc = g_W2s + (size_t)(imgbase + bslab(s)) * SMB_SZ;
            CP_BULK(sb + SMO_B + bbuff(s) * SMB_SZ, bsrc, SMB_SZ, mb);
        }
    };

    if (tid == 0) issue(0);

    float acc[2][12][4];
#pragma unroll
    for (int i = 0; i < 2; i++)
#pragma unroll
        for (int j = 0; j < 12; j++)
#pragma unroll
            for (int k = 0; k < 4; k++) acc[i][j][k] = 0.0f;

    const int aL_row = ((lane >> 3) & 1) * 8 + (lane & 7);
    const int aL_k   = (lane >> 4);
    const int bL_n   = (lane >> 4) * 8 + (lane & 7);
    const int bL_k   = (lane >> 3) & 1;

    for (int s = 0; s < 12; s++) {
        if (s < 11 && tid == 0) issue(s + 1);

        MBARRIER_WAIT_PARITY(sb + SMO_MB + ((s & 1) << 3), (s >> 1) & 1);

        const uint32_t sa = sb + (s & 1) * SMA_SZ;
        const uint32_t sB = sb + SMO_B + bbuff(s) * SMB_SZ;

#pragma unroll
        for (int kk = 0; kk < 4; kk++) {
            uint32_t afr[2][4];
#pragma unroll
            for (int sub = 0; sub < 2; sub++) {
                int row = warpM + sub * 16 + aL_row;
                uint32_t off = sw128((uint32_t)(row * 128 + (kk * 2 + aL_k) * 16));
                LDSM_X4(afr[sub][0], afr[sub][1], afr[sub][2], afr[sub][3], sa + off);
            }
#pragma unroll
            for (int p = 0; p < 6; p++) {
                uint32_t b0, b1, b2, b3;
                int n = warpN + p * 16 + bL_n;
                uint32_t off = sw128((uint32_t)(n * 128 + (kk * 2 + bL_k) * 16));
                LDSM_X4(b0, b1, b2, b3, sB + off);
                MMA_BF16(acc[0][2 * p],     afr[0], b0, b1);
                MMA_BF16(acc[0][2 * p + 1], afr[0], b2, b3);
                MMA_BF16(acc[1][2 * p],     afr[1], b0, b1);
                MMA_BF16(acc[1][2 * p + 1], afr[1], b2, b3);
            }
        }
        __syncthreads();
    }

    // ---- register-level epilogue: tanh.approx activation + masked pooling ----
    {
        const float* __restrict__ bih = dir ? bihr : bihf;
        const float* __restrict__ bhh = dir ? bhhr : bhhf;
        const int g  = lane >> 2;
        const int tg = lane & 3;

        const int vrw  = len - tstart - warpM;
        const int prow = (b << 6) + (tstart >> 5) + (wid & 1);
        const int pcb  = dir * 256 + jhalf * 128 + hb * 32;

        if (vrw <= 0) {
            if (lane < 4) {
#pragma unroll
                for (int q = 0; q < 4; q++)
#pragma unroll
                    for (int c = 0; c < 2; c++) {
                        const int pc = pcb + q * 8 + 2 * tg + c;
                        g_psum[prow * 512 + pc] = 0.0f;
                        g_pmax[prow * 512 + pc] = -1e30f;
                    }
            }
        } else {
            const bool v0 = (g)      < vrw;
            const bool v1 = (g + 8)  < vrw;
            const bool v2 = (g + 16) < vrw;
            const bool v3 = (g + 24) < vrw;
#pragma unroll
            for (int q = 0; q < 4; q++) {
#pragma unroll
                for (int c = 0; c < 2; c++) {
                    const int jl = hb * 32 + q * 8 + 2 * tg + c;
                    const int j  = jhalf * 128 + jl;
                    const float Bi = bih[j]       + bhh[j];
                    const float Bg = bih[512 + j] + bhh[512 + j];
                    const float Bo = bih[768 + j] + bhh[768 + j];

                    float iv[4] = {acc[0][q][c],     acc[0][q][2 + c],
                                   acc[1][q][c],     acc[1][q][2 + c]};
                    float gv[4] = {acc[0][4 + q][c], acc[0][4 + q][2 + c],
                                   acc[1][4 + q][c], acc[1][4 + q][2 + c]};
                    float ov[4] = {acc[0][8 + q][c], acc[0][8 + q][2 + c],
                                   acc[1][8 + q][c], acc[1][8 + q][2 + c]};
                    const bool vld[4] = {v0, v1, v2, v3};

                    float s = 0.0f, m = -1e30f;
#pragma unroll
                    for (int r = 0; r < 4; r++) {
                        float si = fmaf(0.5f, tanha(0.5f * (iv[r] + Bi)), 0.5f);
                        float cs = si * tanha(gv[r] + Bg);
                        float so = fmaf(0.5f, tanha(0.5f * (ov[r] + Bo)), 0.5f);
                        float h  = so * tanha(cs);
                        if (vld[r]) { s += h; m = fmaxf(m, h); }
                    }
#pragma unroll
                    for (int off = 4; off < 32; off <<= 1) {
                        s += __shfl_xor_sync(0xFFFFFFFFu, s, off);
                        m = fmaxf(m, __shfl_xor_sync(0xFFFFFFFFu, m, off));
                    }
                    if (g == 0) {
                        const int pc = pcb + q * 8 + 2 * tg + c;
                        g_psum[prow * 512 + pc] = s;
                        g_pmax[prow * 512 + pc] = m;
                    }
                }
            }
        }
    }

    __syncthreads();
    if (tid == 0) {
        MBARRIER_INVAL(sb + SMO_MB);
        MBARRIER_INVAL(sb + SMO_MB + 8);
    }
}

// ---------------------------------------------------------------------------
// Tail kernel 1: reduce 64 partials -> doc, coalesced.
// Grid (8, 32): block (colgroup64, b). Warp w handles partials w, w+8, ..,
// lanes span 32 consecutive cols (128 B coalesced). SMEM combine.
// ---------------------------------------------------------------------------
__global__ void reduce_kernel(const int* __restrict__ lengths)
{
    __shared__ float ss[8][64];
    __shared__ float sm[8][64];
    const int b    = blockIdx.y;
    const int cb   = blockIdx.x * 64;
    const int tid  = threadIdx.x;
    const int w    = tid >> 5;
    const int lane = tid & 31;

    int len = lengths[b];
    if (len < 1) len = 1;
    if (len > Tt) len = Tt;

    const float* ps = g_psum + (size_t)b * NPART * 512 + cb;
    const float* pm = g_pmax + (size_t)b * NPART * 512 + cb;

    float s0 = 0.f, s1 = 0.f, m0 = -1e30f, m1 = -1e30f;
#pragma unroll
    for (int k = 0; k < 8; k++) {
        const int p = w + k * 8;
        s0 += ps[p * 512 + lane];
        s1 += ps[p * 512 + 32 + lane];
        m0 = fmaxf(m0, pm[p * 512 + lane]);
        m1 = fmaxf(m1, pm[p * 512 + 32 + lane]);
    }
    ss[w][lane] = s0; ss[w][32 + lane] = s1;
    sm[w][lane] = m0; sm[w][32 + lane] = m1;
    __syncthreads();

    if (tid < 64) {
        float S = 0.f, M = -1e30f;
#pragma unroll
        for (int w2 = 0; w2 < 8; w2++) {
            S += ss[w2][tid];
            M = fmaxf(M, sm[w2][tid]);
        }
        g_doc[b * 1024 + cb + tid]       = fmaxf(S / (float)len, 0.0f);
        g_doc[b * 1024 + 512 + cb + tid] = fmaxf(M, 0.0f);
    }
}

// ---------------------------------------------------------------------------
// Tail kernel 2: layer 1. Grid (8, 32).
// ---------------------------------------------------------------------------
__global__ void mlp1_kernel(const float* __restrict__ W1, const float* __restrict__ b1)
{
    __shared__ float doc[1024];
    const int b   = blockIdx.y;
    const int og  = blockIdx.x;
    const int tid = threadIdx.x;
    const int wid = tid >> 5;
    const int lane = tid & 31;

    *(float4*)&doc[tid * 4] = *(const float4*)&g_doc[b * 1024 + tid * 4];
    __syncthreads();

    const int n0 = og * 32 + wid * 4;
    const float* __restrict__ w0 = W1 + (size_t)(n0 + 0) * 1024;
    const float* __restrict__ w1 = W1 + (size_t)(n0 + 1) * 1024;
    const float* __restrict__ w2 = W1 + (size_t)(n0 + 2) * 1024;
    const float* __restrict__ w3 = W1 + (size_t)(n0 + 3) * 1024;

    float s0 = 0.f, s1 = 0.f, s2 = 0.f, s3 = 0.f;
#pragma unroll
    for (int k = lane; k < 1024; k += 32) {
        const float d = doc[k];
        s0 = fmaf(w0[k], d, s0);
        s1 = fmaf(w1[k], d, s1);
        s2 = fmaf(w2[k], d, s2);
        s3 = fmaf(w3[k], d, s3);
    }
#pragma unroll
    for (int off = 16; off > 0; off >>= 1) {
        s0 += __shfl_xor_sync(0xFFFFFFFFu, s0, off);
        s1 += __shfl_xor_sync(0xFFFFFFFFu, s1, off);
        s2 += __shfl_xor_sync(0xFFFFFFFFu, s2, off);
        s3 += __shfl_xor_sync(0xFFFFFFFFu, s3, off);
    }
    if (lane == 0) {
        g_d1[b * 256 + n0 + 0] = s0 + b1[n0 + 0];
        g_d1[b * 256 + n0 + 1] = s1 + b1[n0 + 1];
        g_d1[b * 256 + n0 + 2] = s2 + b1[n0 + 2];
        g_d1[b * 256 + n0 + 3] = s3 + b1[n0 + 3];
    }
}

// ---------------------------------------------------------------------------
// Tail kernel 3: layer 2. Grid 32.
// ---------------------------------------------------------------------------
__global__ void mlp2_kernel(const float* __restrict__ W2, const float* __restrict__ b2,
                            float* __restrict__ out)
{
    __shared__ float d1s[256];
    const int b   = blockIdx.x;
    const int tid = threadIdx.x;
    const int wid = tid >> 5;
    const int lane = tid & 31;

    d1s[tid] = g_d1[b * 256 + tid];
    __syncthreads();

    for (int m = wid; m < NLBL; m += 8) {
        const float* __restrict__ w2r = W2 + m * 256;
        float s = 0.0f;
#pragma unroll
        for (int k = lane; k < 256; k += 32)
            s = fmaf(w2r[k], d1s[k], s);
#pragma unroll
        for (int off = 16; off > 0; off >>= 1)
            s += __shfl_xor_sync(0xFFFFFFFFu, s, off);
        if (lane == 0) out[b * NLBL + m] = s + b2[m];
    }
}

// ---------------------------------------------------------------------------
extern "C" void kernel_launch(void* const* d_in, const int* in_sizes, int n_in,
                              void* d_out, int out_size)
{
    const float* X    = (const float*)d_in[0];
    const int*   lens = (const int*)  d_in[1];
    const float* Wf   = (const float*)d_in[2];
    const float* bihf = (const float*)d_in[3];
    const float* bhhf = (const float*)d_in[4];
    const float* Wr   = (const float*)d_in[5];
    const float* bihr = (const float*)d_in[6];
    const float* bhhr = (const float*)d_in[7];
    const float* W1   = (const float*)d_in[8];
    const float* b1   = (const float*)d_in[9];
    const float* W2   = (const float*)d_in[10];
    const float* b2   = (const float*)d_in[11];
    float* out = (float*)d_out;

    cudaFuncSetAttribute(gemm_mma_kernel, cudaFuncAttributeMaxDynamicSharedMemorySize, SMEM_GEMM);

    conv_x_kernel<<<8192, 256>>>(X, lens);
    conv_w_kernel<<<192, 256>>>(Wf, Wr);

    dim3 gG(4, 1024);
    gemm_mma_kernel<<<gG, 256, SMEM_GEMM>>>(lens, bihf, bhhf, bihr, bhhr);

    dim3 gR(8, Bb);
    reduce_kernel<<<gR, 256>>>(lens);
    dim3 gM1(8, Bb);
    mlp1_kernel<<<gM1, 256>>>(W1, b1);
    mlp2_kernel<<<Bb, 256>>>(W2, b2, out);
}